// round 6
// baseline (speedup 1.0000x reference)
#include <cuda_runtime.h>

#define BB   8
#define NN   512
#define TT   64
#define NINF 64
#define NH   128
#define NODES (BB*NN)   // 4096

// ---------------- scratch (device globals; no allocation allowed) ----------
__device__ float g_An[BB*NN*NN];    // normalized adjacency, 8.4 MB
__device__ float g_dinv[BB*NN];
__device__ float g_W2[256*512];     // [Wcomb(128x512) ; Whcomb(128x512)]
__device__ float g_cb[512];         // per-gate constant bias (bpe@W_bot + bi + bh)
__device__ float g_C[NODES*512];    // per-node constant gate term, 8.4 MB
__device__ float g_h[NODES*NH];
__device__ float g_c[NODES*NH];
__device__ float g_H[NODES*NH];

__device__ __forceinline__ float sigm(float x)  { return 1.0f / (1.0f + __expf(-x)); }
__device__ __forceinline__ float tanhf_(float x){ return 2.0f / (1.0f + __expf(-2.0f*x)) - 1.0f; }

// ---------------- setup kernels --------------------------------------------

// row degrees -> dinv = d>0 ? rsqrt(d) : 0     (grid 512, block 256: 1 warp/row)
__global__ void k_deg(const float* __restrict__ A) {
    int row  = blockIdx.x * 8 + (threadIdx.x >> 5);   // 0..4095
    int lane = threadIdx.x & 31;
    const float* a = A + (size_t)row * NN;
    float s = 0.f;
    #pragma unroll 4
    for (int m = lane; m < NN; m += 32) s += a[m];
    #pragma unroll
    for (int o = 16; o; o >>= 1) s += __shfl_down_sync(0xffffffffu, s, o);
    if (lane == 0) g_dinv[row] = (s > 0.f) ? rsqrtf(s) : 0.f;
}

// An[b,n,m] = A * dinv[b,n] * dinv[b,m]        (grid 2048, block 256, float4)
__global__ void k_norm(const float* __restrict__ A) {
    int idx  = blockIdx.x * blockDim.x + threadIdx.x;  // float4 index, 524288 total
    int rowg = idx >> 7;          // 128 float4 per row
    int m4   = idx & 127;
    int b    = rowg >> 9;
    float di = g_dinv[rowg];
    float4 a = ((const float4*)A)[idx];
    const float* dj = g_dinv + b * NN + m4 * 4;
    float4 r;
    r.x = a.x * di * dj[0];
    r.y = a.y * di * dj[1];
    r.z = a.z * di * dj[2];
    r.w = a.w * di * dj[3];
    ((float4*)g_An)[idx] = r;
}

// W2 rows 0..127: Wpe @ W*[128:,:]; rows 128..255: Wh*     (grid 128, block 256)
__global__ void k_w2(const float* __restrict__ Wpe,
                     const float* Wii, const float* Wif, const float* Wig, const float* Wio,
                     const float* Whi, const float* Whf, const float* Whg, const float* Who) {
    __shared__ float sp[128];
    int k = blockIdx.x;
    if (threadIdx.x < 128) sp[threadIdx.x] = Wpe[k * 128 + threadIdx.x];
    __syncthreads();
    for (int c = threadIdx.x; c < 512; c += blockDim.x) {
        int g = c >> 7, j = c & 127;
        const float* Wg = (g == 0) ? Wii : (g == 1) ? Wif : (g == 2) ? Wig : Wio;
        const float* Wh = (g == 0) ? Whi : (g == 1) ? Whf : (g == 2) ? Whg : Who;
        float s = 0.f;
        #pragma unroll 8
        for (int r = 0; r < 128; r++) s += sp[r] * Wg[(128 + r) * 128 + j];
        g_W2[k * 512 + c]         = s;
        g_W2[(128 + k) * 512 + c] = Wh[k * 128 + j];
    }
}

// cb[g*128+j] = bpe @ Wg[128:,j] + bi_g[j] + bh_g[j]       (1 block, 512 threads)
__global__ void k_cb(const float* __restrict__ bpe,
                     const float* Wii, const float* Wif, const float* Wig, const float* Wio,
                     const float* bii, const float* bif, const float* bgg, const float* bio,
                     const float* bhi, const float* bhf, const float* bhg, const float* bho) {
    int c = threadIdx.x, g = c >> 7, j = c & 127;
    const float* Wg = (g == 0) ? Wii : (g == 1) ? Wif : (g == 2) ? Wig : Wio;
    const float* bi = (g == 0) ? bii : (g == 1) ? bif : (g == 2) ? bgg : bio;
    const float* bh = (g == 0) ? bhi : (g == 1) ? bhf : (g == 2) ? bhg : bho;
    float s = bi[j] + bh[j];
    #pragma unroll 8
    for (int r = 0; r < 128; r++) s += bpe[r] * Wg[(128 + r) * 128 + j];
    g_cb[c] = s;
}

// per-node: es = X0@Wse+bse ; C = es@W*[:128,:] + cb ; zero h,c ; out[t=0]=X0
// grid 4096, block 128
__global__ void k_node(const float* __restrict__ X,
                       const float* __restrict__ Wse, const float* __restrict__ bse,
                       const float* Wii, const float* Wif, const float* Wig, const float* Wio,
                       float* __restrict__ out) {
    __shared__ float sx0[64];
    __shared__ float ses[128];
    int node = blockIdx.x;
    int j = threadIdx.x;
    size_t xbase = (size_t)node * TT * NINF;      // X[b,n,0,:]
    if (j < 64) { float v = X[xbase + j]; sx0[j] = v; out[xbase + j] = v; }
    __syncthreads();
    float e = bse[j];
    #pragma unroll 8
    for (int k = 0; k < 64; k++) e += sx0[k] * Wse[k * 128 + j];
    ses[j] = e;
    g_h[node * 128 + j] = 0.f;
    g_c[node * 128 + j] = 0.f;
    __syncthreads();
    #pragma unroll
    for (int g = 0; g < 4; g++) {
        const float* Wg = (g == 0) ? Wii : (g == 1) ? Wif : (g == 2) ? Wig : Wio;
        float s = g_cb[g * 128 + j];
        #pragma unroll 8
        for (int k = 0; k < 128; k++) s += ses[k] * Wg[k * 128 + j];
        g_C[(size_t)node * 512 + g * 128 + j] = s;
    }
}

// ---------------- per-step kernels ------------------------------------------

// H = An @ h     (grid 128 = 8 batches x 16 row-tiles of 32, block 256)
__global__ void __launch_bounds__(256) k_H() {
    __shared__ float sA[32][36];     // An tile [m_out][k]
    __shared__ float sB[32][132];    // h tile  [k][feat]
    int b    = blockIdx.x >> 4;
    int row0 = (blockIdx.x & 15) * 32;
    int tid  = threadIdx.x;
    int tx   = tid & 31;             // feature group (4 cols)
    int ty   = tid >> 5;             // row group (4 rows)
    const float* An = g_An + (size_t)b * NN * NN;
    const float* hb = g_h  + (size_t)b * NN * NH;
    float acc[4][4] = {};
    int la_r = tid >> 3;             // 0..31
    int la_c = (tid & 7) * 4;        // 0..28
    for (int kb = 0; kb < 16; kb++) {
        *(float4*)&sA[la_r][la_c] =
            *(const float4*)&An[(size_t)(row0 + la_r) * NN + kb * 32 + la_c];
        #pragma unroll
        for (int p = 0; p < 4; p++) {
            int id = tid + p * 256;           // float4 id 0..1023
            int r = id >> 5, c4 = id & 31;
            *(float4*)&sB[r][c4 * 4] =
                *(const float4*)&hb[(size_t)(kb * 32 + r) * NH + c4 * 4];
        }
        __syncthreads();
        #pragma unroll
        for (int k = 0; k < 32; k++) {
            float4 bv = *(float4*)&sB[k][tx * 4];
            #pragma unroll
            for (int i = 0; i < 4; i++) {
                float a = sA[ty * 4 + i][k];
                acc[i][0] += a * bv.x; acc[i][1] += a * bv.y;
                acc[i][2] += a * bv.z; acc[i][3] += a * bv.w;
            }
        }
        __syncthreads();
    }
    #pragma unroll
    for (int i = 0; i < 4; i++) {
        float4 v = make_float4(acc[i][0], acc[i][1], acc[i][2], acc[i][3]);
        *(float4*)&g_H[(size_t)(b * NN + row0 + ty * 4 + i) * NH + tx * 4] = v;
    }
}

// pre = [H|h] @ W2 + C -> LSTM update -> out[t] = out[t-1] + h_t@Wout + bout
// grid 128, block 256
__global__ void __launch_bounds__(256) k_step(const float* __restrict__ Wout,
                                              const float* __restrict__ bout,
                                              float* __restrict__ out, int t) {
    __shared__ float sX[32][260];    // [row][0..127]=H, [128..255]=h ; later h_t in 0..127
    __shared__ float sW[2048];       // streamed weight tile
    int b    = blockIdx.x >> 4;
    int row0 = (blockIdx.x & 15) * 32;
    int tid  = threadIdx.x;
    int tx   = tid & 31;             // j group: cols tx*4..+3 in each gate
    int ty   = tid >> 5;             // rows ty*4..+3
    int nodeBase = b * NN + row0;

    // load [H | h] tile
    #pragma unroll
    for (int p = 0; p < 8; p++) {
        int id = tid + p * 256;      // float4 id 0..2047
        int r  = id >> 6;            // 64 float4 per row
        int c4 = id & 63;
        float4 v;
        if (c4 < 32) v = *(const float4*)&g_H[(size_t)(nodeBase + r) * NH + c4 * 4];
        else         v = *(const float4*)&g_h[(size_t)(nodeBase + r) * NH + (c4 - 32) * 4];
        *(float4*)&sX[r][c4 * 4] = v;
    }
    __syncthreads();

    // gate GEMM: pre[32][512] = sX[32][256] @ W2[256][512]
    float acc[4][4][4] = {};         // [row i][gate g][col q]
    for (int kc = 0; kc < 64; kc++) {
        __syncthreads();
        *(float4*)&sW[tid * 8]     = *(const float4*)&g_W2[kc * 2048 + tid * 8];
        *(float4*)&sW[tid * 8 + 4] = *(const float4*)&g_W2[kc * 2048 + tid * 8 + 4];
        __syncthreads();
        #pragma unroll
        for (int kk = 0; kk < 4; kk++) {
            int K = kc * 4 + kk;
            float a0 = sX[ty * 4 + 0][K];
            float a1 = sX[ty * 4 + 1][K];
            float a2 = sX[ty * 4 + 2][K];
            float a3 = sX[ty * 4 + 3][K];
            #pragma unroll
            for (int g = 0; g < 4; g++) {
                float4 w = *(float4*)&sW[kk * 512 + g * 128 + tx * 4];
                acc[0][g][0] += a0 * w.x; acc[0][g][1] += a0 * w.y;
                acc[0][g][2] += a0 * w.z; acc[0][g][3] += a0 * w.w;
                acc[1][g][0] += a1 * w.x; acc[1][g][1] += a1 * w.y;
                acc[1][g][2] += a1 * w.z; acc[1][g][3] += a1 * w.w;
                acc[2][g][0] += a2 * w.x; acc[2][g][1] += a2 * w.y;
                acc[2][g][2] += a2 * w.z; acc[2][g][3] += a2 * w.w;
                acc[3][g][0] += a3 * w.x; acc[3][g][1] += a3 * w.y;
                acc[3][g][2] += a3 * w.z; acc[3][g][3] += a3 * w.w;
            }
        }
    }
    __syncthreads();

    // LSTM elementwise (thread owns all 4 gates for its (row, j) quad)
    #pragma unroll
    for (int i = 0; i < 4; i++) {
        int row = ty * 4 + i;
        size_t gn = (size_t)(nodeBase + row);
        float4 ci = *(const float4*)&g_C[gn * 512 +   0 + tx * 4];
        float4 cf = *(const float4*)&g_C[gn * 512 + 128 + tx * 4];
        float4 cg = *(const float4*)&g_C[gn * 512 + 256 + tx * 4];
        float4 co = *(const float4*)&g_C[gn * 512 + 384 + tx * 4];
        float4 cold = *(const float4*)&g_c[gn * 128 + tx * 4];
        const float* cip = (const float*)&ci;
        const float* cfp = (const float*)&cf;
        const float* cgp = (const float*)&cg;
        const float* cop = (const float*)&co;
        const float* clp = (const float*)&cold;
        float hn[4], cn[4];
        #pragma unroll
        for (int q = 0; q < 4; q++) {
            float ig = sigm (acc[i][0][q] + cip[q]);
            float fg = sigm (acc[i][1][q] + cfp[q]);
            float gg = tanhf_(acc[i][2][q] + cgp[q]);
            float og = sigm (acc[i][3][q] + cop[q]);
            float cc = fg * clp[q] + ig * gg;
            cn[q] = cc;
            hn[q] = og * tanhf_(cc);
        }
        *(float4*)&g_c[gn * 128 + tx * 4] = make_float4(cn[0], cn[1], cn[2], cn[3]);
        float4 hv = make_float4(hn[0], hn[1], hn[2], hn[3]);
        *(float4*)&g_h[gn * 128 + tx * 4] = hv;
        *(float4*)&sX[row][tx * 4] = hv;          // h_t staged for output GEMM
    }
    __syncthreads();

    // output GEMM: out[t] = out[t-1] + h_t[32][128] @ Wout[128][64] + bout
    int orow = tid >> 3;             // 0..31
    int oc   = (tid & 7) * 8;        // col base (8 cols)
    float oa[8] = {};
    for (int ch = 0; ch < 4; ch++) {
        __syncthreads();
        *(float4*)&sW[tid * 8]     = *(const float4*)&Wout[ch * 2048 + tid * 8];
        *(float4*)&sW[tid * 8 + 4] = *(const float4*)&Wout[ch * 2048 + tid * 8 + 4];
        __syncthreads();
        #pragma unroll
        for (int k = 0; k < 32; k++) {
            float hv  = sX[orow][ch * 32 + k];
            float4 w0 = *(float4*)&sW[k * 64 + oc];
            float4 w1 = *(float4*)&sW[k * 64 + oc + 4];
            oa[0] += hv * w0.x; oa[1] += hv * w0.y; oa[2] += hv * w0.z; oa[3] += hv * w0.w;
            oa[4] += hv * w1.x; oa[5] += hv * w1.y; oa[6] += hv * w1.z; oa[7] += hv * w1.w;
        }
    }
    size_t gn = (size_t)(nodeBase + orow);
    size_t obase = (gn * TT + t) * NINF + oc;
    float4 p0 = *(const float4*)&out[obase - NINF];
    float4 p1 = *(const float4*)&out[obase - NINF + 4];
    float4 b0 = *(const float4*)&bout[oc];
    float4 b1 = *(const float4*)&bout[oc + 4];
    float4 r0 = make_float4(p0.x + oa[0] + b0.x, p0.y + oa[1] + b0.y,
                            p0.z + oa[2] + b0.z, p0.w + oa[3] + b0.w);
    float4 r1 = make_float4(p1.x + oa[4] + b1.x, p1.y + oa[5] + b1.y,
                            p1.z + oa[6] + b1.z, p1.w + oa[7] + b1.w);
    *(float4*)&out[obase]     = r0;
    *(float4*)&out[obase + 4] = r1;
}

// ---------------- launch -----------------------------------------------------

extern "C" void kernel_launch(void* const* d_in, const int* in_sizes, int n_in,
                              void* d_out, int out_size) {
    (void)in_sizes; (void)n_in; (void)out_size;
    const float* X    = (const float*)d_in[0];
    const float* A    = (const float*)d_in[1];
    const float* Wse  = (const float*)d_in[2];
    const float* bse  = (const float*)d_in[3];
    const float* Wpe  = (const float*)d_in[4];
    const float* bpe  = (const float*)d_in[5];
    const float* Wii  = (const float*)d_in[6];
    const float* bii  = (const float*)d_in[7];
    const float* Whi  = (const float*)d_in[8];
    const float* bhi  = (const float*)d_in[9];
    const float* Wif  = (const float*)d_in[10];
    const float* bif  = (const float*)d_in[11];
    const float* Whf  = (const float*)d_in[12];
    const float* bhf  = (const float*)d_in[13];
    const float* Wig  = (const float*)d_in[14];
    const float* bgg  = (const float*)d_in[15];
    const float* Whg  = (const float*)d_in[16];
    const float* bhg  = (const float*)d_in[17];
    const float* Wio  = (const float*)d_in[18];
    const float* bio  = (const float*)d_in[19];
    const float* Who  = (const float*)d_in[20];
    const float* bho  = (const float*)d_in[21];
    const float* Wout = (const float*)d_in[22];
    const float* bout = (const float*)d_in[23];
    float* out = (float*)d_out;

    k_deg <<<512,  256>>>(A);
    k_norm<<<2048, 256>>>(A);
    k_w2  <<<128,  256>>>(Wpe, Wii, Wif, Wig, Wio, Whi, Whf, Whg, Who);
    k_cb  <<<1,    512>>>(bpe, Wii, Wif, Wig, Wio,
                          bii, bif, bgg, bio, bhi, bhf, bhg, bho);
    k_node<<<4096, 128>>>(X, Wse, bse, Wii, Wif, Wig, Wio, out);

    for (int t = 1; t < TT; t++) {
        k_H   <<<128, 256>>>();
        k_step<<<128, 256>>>(Wout, bout, out, t);
    }
}

// round 7
// speedup vs baseline: 1.0305x; 1.0305x over previous
#include <cuda_runtime.h>

#define BB   8
#define NN   512
#define TT   64
#define NINF 64
#define NH   128
#define NODES (BB*NN)   // 4096

// ---------------- scratch (device globals; no allocation allowed) ----------
__device__ float g_An[BB*NN*NN];    // normalized adjacency, 8.4 MB
__device__ float g_dinv[BB*NN];
__device__ float g_W2[256*512];     // [Wcomb(128x512) ; Whcomb(128x512)]
__device__ float g_cb[512];         // per-gate constant bias (bpe@W_bot + bi + bh)
__device__ float g_C[NODES*512];    // per-node constant gate term, 8.4 MB
__device__ float g_h[NODES*NH];
__device__ float g_c[NODES*NH];

typedef unsigned long long u64;

__device__ __forceinline__ u64 pk2(float x) {
    u64 r; asm("mov.b64 %0, {%1,%1};" : "=l"(r) : "f"(x)); return r;
}
__device__ __forceinline__ void ffma2(u64 &d, u64 a, u64 b) {
    asm("fma.rn.f32x2 %0, %1, %2, %0;" : "+l"(d) : "l"(a), "l"(b));
}
__device__ __forceinline__ float2 up2(u64 v) {
    float2 r; asm("mov.b64 {%0, %1}, %2;" : "=f"(r.x), "=f"(r.y) : "l"(v)); return r;
}

__device__ __forceinline__ float sigm(float x)  { return 1.0f / (1.0f + __expf(-x)); }
__device__ __forceinline__ float tanhf_(float x){ return 2.0f / (1.0f + __expf(-2.0f*x)) - 1.0f; }

// ---------------- setup kernels --------------------------------------------

// row degrees -> dinv = d>0 ? rsqrt(d) : 0     (grid 512, block 256: 1 warp/row)
__global__ void k_deg(const float* __restrict__ A) {
    int row  = blockIdx.x * 8 + (threadIdx.x >> 5);   // 0..4095
    int lane = threadIdx.x & 31;
    const float* a = A + (size_t)row * NN;
    float s = 0.f;
    #pragma unroll 4
    for (int m = lane; m < NN; m += 32) s += a[m];
    #pragma unroll
    for (int o = 16; o; o >>= 1) s += __shfl_down_sync(0xffffffffu, s, o);
    if (lane == 0) g_dinv[row] = (s > 0.f) ? rsqrtf(s) : 0.f;
}

// An[b,n,m] = A * dinv[b,n] * dinv[b,m]        (grid 2048, block 256, float4)
__global__ void k_norm(const float* __restrict__ A) {
    int idx  = blockIdx.x * blockDim.x + threadIdx.x;  // float4 index, 524288 total
    int rowg = idx >> 7;          // 128 float4 per row
    int m4   = idx & 127;
    int b    = rowg >> 9;
    float di = g_dinv[rowg];
    float4 a = ((const float4*)A)[idx];
    const float* dj = g_dinv + b * NN + m4 * 4;
    float4 r;
    r.x = a.x * di * dj[0];
    r.y = a.y * di * dj[1];
    r.z = a.z * di * dj[2];
    r.w = a.w * di * dj[3];
    ((float4*)g_An)[idx] = r;
}

// W2 rows 0..127: Wpe @ W*[128:,:]; rows 128..255: Wh*     (grid 128, block 256)
__global__ void k_w2(const float* __restrict__ Wpe,
                     const float* Wii, const float* Wif, const float* Wig, const float* Wio,
                     const float* Whi, const float* Whf, const float* Whg, const float* Who) {
    __shared__ float sp[128];
    int k = blockIdx.x;
    if (threadIdx.x < 128) sp[threadIdx.x] = Wpe[k * 128 + threadIdx.x];
    __syncthreads();
    for (int c = threadIdx.x; c < 512; c += blockDim.x) {
        int g = c >> 7, j = c & 127;
        const float* Wg = (g == 0) ? Wii : (g == 1) ? Wif : (g == 2) ? Wig : Wio;
        const float* Wh = (g == 0) ? Whi : (g == 1) ? Whf : (g == 2) ? Whg : Who;
        float s = 0.f;
        #pragma unroll 8
        for (int r = 0; r < 128; r++) s += sp[r] * Wg[(128 + r) * 128 + j];
        g_W2[k * 512 + c]         = s;
        g_W2[(128 + k) * 512 + c] = Wh[k * 128 + j];
    }
}

// cb[g*128+j] = bpe @ Wg[128:,j] + bi_g[j] + bh_g[j]       (1 block, 512 threads)
__global__ void k_cb(const float* __restrict__ bpe,
                     const float* Wii, const float* Wif, const float* Wig, const float* Wio,
                     const float* bii, const float* bif, const float* bgg, const float* bio,
                     const float* bhi, const float* bhf, const float* bhg, const float* bho) {
    int c = threadIdx.x, g = c >> 7, j = c & 127;
    const float* Wg = (g == 0) ? Wii : (g == 1) ? Wif : (g == 2) ? Wig : Wio;
    const float* bi = (g == 0) ? bii : (g == 1) ? bif : (g == 2) ? bgg : bio;
    const float* bh = (g == 0) ? bhi : (g == 1) ? bhf : (g == 2) ? bhg : bho;
    float s = bi[j] + bh[j];
    #pragma unroll 8
    for (int r = 0; r < 128; r++) s += bpe[r] * Wg[(128 + r) * 128 + j];
    g_cb[c] = s;
}

// per-node: es = X0@Wse+bse ; C = es@W*[:128,:] + cb ; zero h,c ; out[t=0]=X0
// grid 4096, block 128
__global__ void k_node(const float* __restrict__ X,
                       const float* __restrict__ Wse, const float* __restrict__ bse,
                       const float* Wii, const float* Wif, const float* Wig, const float* Wio,
                       float* __restrict__ out) {
    __shared__ float sx0[64];
    __shared__ float ses[128];
    int node = blockIdx.x;
    int j = threadIdx.x;
    size_t xbase = (size_t)node * TT * NINF;      // X[b,n,0,:]
    if (j < 64) { float v = X[xbase + j]; sx0[j] = v; out[xbase + j] = v; }
    __syncthreads();
    float e = bse[j];
    #pragma unroll 8
    for (int k = 0; k < 64; k++) e += sx0[k] * Wse[k * 128 + j];
    ses[j] = e;
    g_h[node * 128 + j] = 0.f;
    g_c[node * 128 + j] = 0.f;
    __syncthreads();
    #pragma unroll
    for (int g = 0; g < 4; g++) {
        const float* Wg = (g == 0) ? Wii : (g == 1) ? Wif : (g == 2) ? Wig : Wio;
        float s = g_cb[g * 128 + j];
        #pragma unroll 8
        for (int k = 0; k < 128; k++) s += ses[k] * Wg[k * 128 + j];
        g_C[(size_t)node * 512 + g * 128 + j] = s;
    }
}

// ---------------- fused per-step kernel -------------------------------------
// Phase A: H_tile = An[row0:+32,:] @ h_b   (stays in SMEM)
// Phase B: pre = [H|h] @ W2 + C -> LSTM -> out[t] = out[t-1] + h_t@Wout + bout
// grid 128 (= 8 batches x 16 row-tiles of 32), block 256
__global__ void __launch_bounds__(256) k_fused(const float* __restrict__ Wout,
                                               const float* __restrict__ bout,
                                               float* __restrict__ out, int t) {
    __shared__ float sX[32][256];    // phase B: [row][0..127]=H, [128..255]=h; later h_t
    __shared__ float sW[2][2048];    // double-buffered weight tiles
    // phase A aliases the sX region (4608 + 16896 = 21504 B < 32768 B)
    float (*sA)[36]  = (float (*)[36])  &sX[0][0];
    float (*sB)[132] = (float (*)[132]) (&sX[0][0] + 32 * 36);

    int b    = blockIdx.x >> 4;
    int row0 = (blockIdx.x & 15) * 32;
    int tid  = threadIdx.x;
    int tx   = tid & 31;             // col group (4 cols)
    int ty   = tid >> 5;             // row group (4 rows)
    int nodeBase = b * NN + row0;
    const float* An = g_An + (size_t)b * NN * NN;
    const float* hb = g_h  + (size_t)b * NN * NH;

    // ---------------- Phase A: H tile via packed FFMA2 ----------------
    u64 hacc[4][2] = {};
    int la_r = tid >> 3;             // 0..31
    int la_c = (tid & 7) * 4;        // 0..28
    for (int kb = 0; kb < 16; kb++) {
        __syncthreads();             // all reads of sA/sB from prev iter done
        *(float4*)&sA[la_r][la_c] =
            *(const float4*)&An[(size_t)(row0 + la_r) * NN + kb * 32 + la_c];
        #pragma unroll
        for (int p = 0; p < 4; p++) {
            int id = tid + p * 256;           // float4 id 0..1023
            int r = id >> 5, c4 = id & 31;
            *(float4*)&sB[r][c4 * 4] =
                *(const float4*)&hb[(size_t)(kb * 32 + r) * NH + c4 * 4];
        }
        __syncthreads();
        #pragma unroll
        for (int k = 0; k < 32; k++) {
            ulonglong2 bv = *(ulonglong2*)&sB[k][tx * 4];
            #pragma unroll
            for (int i = 0; i < 4; i++) {
                u64 aa = pk2(sA[ty * 4 + i][k]);
                ffma2(hacc[i][0], aa, bv.x);
                ffma2(hacc[i][1], aa, bv.y);
            }
        }
    }
    __syncthreads();

    // H -> sX[r][0..127]; load h tile -> sX[r][128..255]
    #pragma unroll
    for (int i = 0; i < 4; i++) {
        float2 v0 = up2(hacc[i][0]);
        float2 v1 = up2(hacc[i][1]);
        *(float4*)&sX[ty * 4 + i][tx * 4] = make_float4(v0.x, v0.y, v1.x, v1.y);
    }
    #pragma unroll
    for (int p = 0; p < 4; p++) {
        int id = tid + p * 256;      // 1024 float4 = 32 rows x 32
        int r = id >> 5, c4 = id & 31;
        *(float4*)&sX[r][128 + c4 * 4] =
            *(const float4*)&hb[(size_t)(row0 + r) * NH + c4 * 4];
    }
    // prefetch first W2 tile into sW[0]
    *(float4*)&sW[0][tid * 8]     = *(const float4*)&g_W2[tid * 8];
    *(float4*)&sW[0][tid * 8 + 4] = *(const float4*)&g_W2[tid * 8 + 4];
    __syncthreads();

    // ---------------- Phase B1: gate GEMM, double-buffered, FFMA2 ------
    u64 acc[4][4][2] = {};           // [row i][gate g][col-pair]
    for (int kc = 0; kc < 64; kc++) {
        int cur = kc & 1;
        if (kc < 63) {               // prefetch next tile (buffer cur^1 is free)
            *(float4*)&sW[cur ^ 1][tid * 8] =
                *(const float4*)&g_W2[(kc + 1) * 2048 + tid * 8];
            *(float4*)&sW[cur ^ 1][tid * 8 + 4] =
                *(const float4*)&g_W2[(kc + 1) * 2048 + tid * 8 + 4];
        }
        float4 av[4];
        #pragma unroll
        for (int i = 0; i < 4; i++) av[i] = *(float4*)&sX[ty * 4 + i][kc * 4];
        #pragma unroll
        for (int kk = 0; kk < 4; kk++) {
            u64 aa[4];
            aa[0] = pk2(((const float*)&av[0])[kk]);
            aa[1] = pk2(((const float*)&av[1])[kk]);
            aa[2] = pk2(((const float*)&av[2])[kk]);
            aa[3] = pk2(((const float*)&av[3])[kk]);
            #pragma unroll
            for (int g = 0; g < 4; g++) {
                ulonglong2 w = *(ulonglong2*)&sW[cur][kk * 512 + g * 128 + tx * 4];
                #pragma unroll
                for (int i = 0; i < 4; i++) {
                    ffma2(acc[i][g][0], aa[i], w.x);
                    ffma2(acc[i][g][1], aa[i], w.y);
                }
            }
        }
        __syncthreads();
    }

    // ---------------- Phase B2: LSTM elementwise ------------------------
    #pragma unroll
    for (int i = 0; i < 4; i++) {
        int row = ty * 4 + i;
        size_t gn = (size_t)(nodeBase + row);
        float4 ci = *(const float4*)&g_C[gn * 512 +   0 + tx * 4];
        float4 cf = *(const float4*)&g_C[gn * 512 + 128 + tx * 4];
        float4 cg = *(const float4*)&g_C[gn * 512 + 256 + tx * 4];
        float4 co = *(const float4*)&g_C[gn * 512 + 384 + tx * 4];
        float4 cold = *(const float4*)&g_c[gn * 128 + tx * 4];
        const float* cip = (const float*)&ci;
        const float* cfp = (const float*)&cf;
        const float* cgp = (const float*)&cg;
        const float* cop = (const float*)&co;
        const float* clp = (const float*)&cold;
        float pre[4][4];
        #pragma unroll
        for (int g = 0; g < 4; g++) {
            float2 a = up2(acc[i][g][0]);
            float2 c2 = up2(acc[i][g][1]);
            pre[g][0] = a.x; pre[g][1] = a.y; pre[g][2] = c2.x; pre[g][3] = c2.y;
        }
        float hn[4], cn[4];
        #pragma unroll
        for (int q = 0; q < 4; q++) {
            float ig = sigm  (pre[0][q] + cip[q]);
            float fg = sigm  (pre[1][q] + cfp[q]);
            float gg = tanhf_(pre[2][q] + cgp[q]);
            float og = sigm  (pre[3][q] + cop[q]);
            float cc = fg * clp[q] + ig * gg;
            cn[q] = cc;
            hn[q] = og * tanhf_(cc);
        }
        *(float4*)&g_c[gn * 128 + tx * 4] = make_float4(cn[0], cn[1], cn[2], cn[3]);
        float4 hv = make_float4(hn[0], hn[1], hn[2], hn[3]);
        *(float4*)&g_h[gn * 128 + tx * 4] = hv;
        *(float4*)&sX[row][tx * 4] = hv;          // h_t staged for output GEMM
    }

    // ---------------- Phase B3: output GEMM, FFMA2 ----------------------
    int orow = tid >> 3;             // 0..31
    int oc   = (tid & 7) * 8;        // col base (8 cols)
    u64 oa[4] = {};
    for (int ch = 0; ch < 4; ch++) {
        __syncthreads();             // (ch=0) also orders h_t writes above
        *(float4*)&sW[0][tid * 8]     = *(const float4*)&Wout[ch * 2048 + tid * 8];
        *(float4*)&sW[0][tid * 8 + 4] = *(const float4*)&Wout[ch * 2048 + tid * 8 + 4];
        __syncthreads();
        #pragma unroll
        for (int k = 0; k < 32; k++) {
            u64 hh = pk2(sX[orow][ch * 32 + k]);
            ulonglong2 w0 = *(ulonglong2*)&sW[0][k * 64 + oc];
            ulonglong2 w1 = *(ulonglong2*)&sW[0][k * 64 + oc + 4];
            ffma2(oa[0], hh, w0.x); ffma2(oa[1], hh, w0.y);
            ffma2(oa[2], hh, w1.x); ffma2(oa[3], hh, w1.y);
        }
    }
    size_t gn = (size_t)(nodeBase + orow);
    size_t obase = (gn * TT + t) * NINF + oc;
    float4 p0 = *(const float4*)&out[obase - NINF];
    float4 p1 = *(const float4*)&out[obase - NINF + 4];
    float4 b0 = *(const float4*)&bout[oc];
    float4 b1 = *(const float4*)&bout[oc + 4];
    float2 o0 = up2(oa[0]), o1 = up2(oa[1]), o2 = up2(oa[2]), o3 = up2(oa[3]);
    float4 r0 = make_float4(p0.x + o0.x + b0.x, p0.y + o0.y + b0.y,
                            p0.z + o1.x + b0.z, p0.w + o1.y + b0.w);
    float4 r1 = make_float4(p1.x + o2.x + b1.x, p1.y + o2.y + b1.y,
                            p1.z + o3.x + b1.z, p1.w + o3.y + b1.w);
    *(float4*)&out[obase]     = r0;
    *(float4*)&out[obase + 4] = r1;
}

// ---------------- launch -----------------------------------------------------

extern "C" void kernel_launch(void* const* d_in, const int* in_sizes, int n_in,
                              void* d_out, int out_size) {
    (void)in_sizes; (void)n_in; (void)out_size;
    const float* X    = (const float*)d_in[0];
    const float* A    = (const float*)d_in[1];
    const float* Wse  = (const float*)d_in[2];
    const float* bse  = (const float*)d_in[3];
    const float* Wpe  = (const float*)d_in[4];
    const float* bpe  = (const float*)d_in[5];
    const float* Wii  = (const float*)d_in[6];
    const float* bii  = (const float*)d_in[7];
    const float* Whi  = (const float*)d_in[8];
    const float* bhi  = (const float*)d_in[9];
    const float* Wif  = (const float*)d_in[10];
    const float* bif  = (const float*)d_in[11];
    const float* Whf  = (const float*)d_in[12];
    const float* bhf  = (const float*)d_in[13];
    const float* Wig  = (const float*)d_in[14];
    const float* bgg  = (const float*)d_in[15];
    const float* Whg  = (const float*)d_in[16];
    const float* bhg  = (const float*)d_in[17];
    const float* Wio  = (const float*)d_in[18];
    const float* bio  = (const float*)d_in[19];
    const float* Who  = (const float*)d_in[20];
    const float* bho  = (const float*)d_in[21];
    const float* Wout = (const float*)d_in[22];
    const float* bout = (const float*)d_in[23];
    float* out = (float*)d_out;

    k_deg <<<512,  256>>>(A);
    k_norm<<<2048, 256>>>(A);
    k_w2  <<<128,  256>>>(Wpe, Wii, Wif, Wig, Wio, Whi, Whf, Whg, Who);
    k_cb  <<<1,    512>>>(bpe, Wii, Wif, Wig, Wio,
                          bii, bif, bgg, bio, bhi, bhf, bhg, bho);
    k_node<<<4096, 128>>>(X, Wse, bse, Wii, Wif, Wig, Wio, out);

    for (int t = 1; t < TT; t++) {
        k_fused<<<128, 256>>>(Wout, bout, out, t);
    }
}

// round 10
// speedup vs baseline: 1.1119x; 1.0791x over previous
#include <cuda_runtime.h>

#define BB   8
#define NN   512
#define TT   64
#define NINF 64
#define NH   128
#define NODES (BB*NN)   // 4096

// ---------------- scratch (device globals; no allocation allowed) ----------
__device__ float g_An[BB*NN*NN];      // normalized adjacency, 8.4 MB
__device__ float g_dinv[BB*NN];
__device__ float g_W2[256*512];       // [Wcomb(128x512) ; Whcomb(128x512)]
__device__ float g_cb[512];           // per-gate constant bias
__device__ float g_C[NODES*512];      // per-node constant gate term, 8.4 MB
__device__ float g_hpp[2*NODES*NH];   // double-buffered hidden state (race-free)
__device__ float g_c[NODES*NH];

typedef unsigned long long u64;

__device__ __forceinline__ u64 pk2(float x) {
    u64 r; asm("mov.b64 %0, {%1,%1};" : "=l"(r) : "f"(x)); return r;
}
__device__ __forceinline__ void ffma2(u64 &d, u64 a, u64 b) {
    asm("fma.rn.f32x2 %0, %1, %2, %0;" : "+l"(d) : "l"(a), "l"(b));
}
__device__ __forceinline__ float2 up2(u64 v) {
    float2 r; asm("mov.b64 {%0, %1}, %2;" : "=f"(r.x), "=f"(r.y) : "l"(v)); return r;
}

__device__ __forceinline__ float sigm(float x)  { return 1.0f / (1.0f + __expf(-x)); }
__device__ __forceinline__ float tanhf_(float x){ return 2.0f / (1.0f + __expf(-2.0f*x)) - 1.0f; }

// ---------------- setup kernels --------------------------------------------

__global__ void k_deg(const float* __restrict__ A) {
    int row  = blockIdx.x * 8 + (threadIdx.x >> 5);
    int lane = threadIdx.x & 31;
    const float* a = A + (size_t)row * NN;
    float s = 0.f;
    #pragma unroll 4
    for (int m = lane; m < NN; m += 32) s += a[m];
    #pragma unroll
    for (int o = 16; o; o >>= 1) s += __shfl_down_sync(0xffffffffu, s, o);
    if (lane == 0) g_dinv[row] = (s > 0.f) ? rsqrtf(s) : 0.f;
}

__global__ void k_norm(const float* __restrict__ A) {
    int idx  = blockIdx.x * blockDim.x + threadIdx.x;
    int rowg = idx >> 7;
    int m4   = idx & 127;
    int b    = rowg >> 9;
    float di = g_dinv[rowg];
    float4 a = ((const float4*)A)[idx];
    const float* dj = g_dinv + b * NN + m4 * 4;
    float4 r;
    r.x = a.x * di * dj[0];
    r.y = a.y * di * dj[1];
    r.z = a.z * di * dj[2];
    r.w = a.w * di * dj[3];
    ((float4*)g_An)[idx] = r;
}

__global__ void k_w2(const float* __restrict__ Wpe,
                     const float* Wii, const float* Wif, const float* Wig, const float* Wio,
                     const float* Whi, const float* Whf, const float* Whg, const float* Who) {
    __shared__ float sp[128];
    int k = blockIdx.x;
    if (threadIdx.x < 128) sp[threadIdx.x] = Wpe[k * 128 + threadIdx.x];
    __syncthreads();
    for (int c = threadIdx.x; c < 512; c += blockDim.x) {
        int g = c >> 7, j = c & 127;
        const float* Wg = (g == 0) ? Wii : (g == 1) ? Wif : (g == 2) ? Wig : Wio;
        const float* Wh = (g == 0) ? Whi : (g == 1) ? Whf : (g == 2) ? Whg : Who;
        float s = 0.f;
        #pragma unroll 8
        for (int r = 0; r < 128; r++) s += sp[r] * Wg[(128 + r) * 128 + j];
        g_W2[k * 512 + c]         = s;
        g_W2[(128 + k) * 512 + c] = Wh[k * 128 + j];
    }
}

__global__ void k_cb(const float* __restrict__ bpe,
                     const float* Wii, const float* Wif, const float* Wig, const float* Wio,
                     const float* bii, const float* bif, const float* bgg, const float* bio,
                     const float* bhi, const float* bhf, const float* bhg, const float* bho) {
    int c = threadIdx.x, g = c >> 7, j = c & 127;
    const float* Wg = (g == 0) ? Wii : (g == 1) ? Wif : (g == 2) ? Wig : Wio;
    const float* bi = (g == 0) ? bii : (g == 1) ? bif : (g == 2) ? bgg : bio;
    const float* bh = (g == 0) ? bhi : (g == 1) ? bhf : (g == 2) ? bhg : bho;
    float s = bi[j] + bh[j];
    #pragma unroll 8
    for (int r = 0; r < 128; r++) s += bpe[r] * Wg[(128 + r) * 128 + j];
    g_cb[c] = s;
}

__global__ void k_node(const float* __restrict__ X,
                       const float* __restrict__ Wse, const float* __restrict__ bse,
                       const float* Wii, const float* Wif, const float* Wig, const float* Wio,
                       float* __restrict__ out) {
    __shared__ float sx0[64];
    __shared__ float ses[128];
    int node = blockIdx.x;
    int j = threadIdx.x;
    size_t xbase = (size_t)node * TT * NINF;
    if (j < 64) { float v = X[xbase + j]; sx0[j] = v; out[xbase + j] = v; }
    __syncthreads();
    float e = bse[j];
    #pragma unroll 8
    for (int k = 0; k < 64; k++) e += sx0[k] * Wse[k * 128 + j];
    ses[j] = e;
    g_hpp[node * 128 + j] = 0.f;     // h_0 in parity-0 buffer
    g_c[node * 128 + j] = 0.f;
    __syncthreads();
    #pragma unroll
    for (int g = 0; g < 4; g++) {
        const float* Wg = (g == 0) ? Wii : (g == 1) ? Wif : (g == 2) ? Wig : Wio;
        float s = g_cb[g * 128 + j];
        #pragma unroll 8
        for (int k = 0; k < 128; k++) s += ses[k] * Wg[k * 128 + j];
        g_C[(size_t)node * 512 + g * 128 + j] = s;
    }
}

// ---------------- fused per-step kernel -------------------------------------
// Phase A: H = An_tile[32x512] @ h  -> transposed into sXT[k][r] (swizzled)
// Phase B: pre = sXT^T @ W2 + C -> LSTM -> out[t] = out[t-1] + h_t@Wout + bout
// grid 128 (= 8 batches x 16 row-tiles of 32), block 256
__global__ void __launch_bounds__(256) k_fused(const float* __restrict__ Wout,
                                               const float* __restrict__ bout,
                                               float* __restrict__ out, int t) {
    __shared__ __align__(16) float sXT[256 * 32];   // 32 KB: [k 0..255][row 0..31], XOR swizzle
    __shared__ __align__(16) float sW[2][2048];     // 16 KB: double-buffered weight chunks
    float* sAT = sXT;                 // phase A: An^T tile, 32k x 32r (words 0..1023)
    float* sB  = sXT + 1024;          // phase A: h tile, 32k x 128f  (words 1024..5119)

    const int tid  = threadIdx.x;
    const int w    = tid >> 5;
    const int lane = tid & 31;
    const int b    = blockIdx.x >> 4;
    const int row0 = (blockIdx.x & 15) * 32;
    const int nodeBase = b * NN + row0;

    const float* hr = g_hpp + ((t - 1) & 1) * (NODES * NH);   // read h_{t-1}
    float*       hw = g_hpp + (t & 1)       * (NODES * NH);   // write h_t
    const float* An = g_An + (size_t)b * NN * NN;

    // ---------------- Phase A: H = An_tile @ h -------------------------
    // warp tile: 32 rows x 16 feats; lane: 4 rows (2 pairs) x 4 feats
    const int r0A = (lane & 7) * 4;
    const int fgA = lane >> 3;
    const int f0A = w * 16 + fgA * 4;
    const int kk4 = tid & 7;          // An loader: k-float4 index
    const int rL  = tid >> 3;         // An loader: row

    u64 accA[2][4] = {};
    for (int kb = 0; kb < 16; kb++) {
        // load An tile transposed (swizzled, conflict-free)
        {
            float4 v = *(const float4*)&An[(size_t)(row0 + rL) * NN + kb * 32 + kk4 * 4];
            int rsw = rL ^ (kk4 << 2);
            sAT[(kk4 * 4 + 0) * 32 + rsw] = v.x;
            sAT[(kk4 * 4 + 1) * 32 + rsw] = v.y;
            sAT[(kk4 * 4 + 2) * 32 + rsw] = v.z;
            sAT[(kk4 * 4 + 3) * 32 + rsw] = v.w;
        }
        // load h tile (natural layout)
        #pragma unroll
        for (int p = 0; p < 4; p++) {
            int id = tid + p * 256;
            int kL = id >> 5, f4 = id & 31;
            *(float4*)&sB[kL * 128 + f4 * 4] =
                *(const float4*)&hr[(size_t)(b * NN + kb * 32 + kL) * NH + f4 * 4];
        }
        __syncthreads();
        #pragma unroll
        for (int k = 0; k < 32; k++) {
            const int sw = ((k >> 2) & 7) << 2;
            ulonglong2 ap = *(ulonglong2*)&sAT[k * 32 + (r0A ^ sw)];
            float4 bf = *(float4*)&sB[k * 128 + f0A];
            u64 b0 = pk2(bf.x), b1 = pk2(bf.y), b2 = pk2(bf.z), b3 = pk2(bf.w);
            ffma2(accA[0][0], ap.x, b0); ffma2(accA[0][1], ap.x, b1);
            ffma2(accA[0][2], ap.x, b2); ffma2(accA[0][3], ap.x, b3);
            ffma2(accA[1][0], ap.y, b0); ffma2(accA[1][1], ap.y, b1);
            ffma2(accA[1][2], ap.y, b2); ffma2(accA[1][3], ap.y, b3);
        }
        __syncthreads();
    }

    // H -> sXT rows 0..127 (transposed, swizzled); h tile -> rows 128..255
    {
        const int swH = ((w * 4 + fgA) & 7) << 2;
        #pragma unroll
        for (int ff = 0; ff < 4; ff++) {
            #pragma unroll
            for (int p = 0; p < 2; p++) {
                int rsw = (r0A + 2 * p) ^ swH;
                *(u64*)&sXT[(f0A + ff) * 32 + rsw] = accA[p][ff];
            }
        }
    }
    #pragma unroll
    for (int p = 0; p < 4; p++) {
        int id = tid + p * 256;
        int r = id & 31, f4 = id >> 5;
        float4 v = *(const float4*)&hr[(size_t)(nodeBase + r) * NH + f4 * 4];
        int rsw = r ^ ((f4 & 7) << 2);
        sXT[(128 + f4 * 4 + 0) * 32 + rsw] = v.x;
        sXT[(128 + f4 * 4 + 1) * 32 + rsw] = v.y;
        sXT[(128 + f4 * 4 + 2) * 32 + rsw] = v.z;
        sXT[(128 + f4 * 4 + 3) * 32 + rsw] = v.w;
    }
    // prefetch W2 chunk 0 (k rows 0..3)
    *(float4*)&sW[0][tid * 8]     = *(const float4*)&g_W2[tid * 8];
    *(float4*)&sW[0][tid * 8 + 4] = *(const float4*)&g_W2[tid * 8 + 4];
    __syncthreads();

    // ---------------- Phase B1: gate GEMM -------------------------------
    // warp owns j-slice [w*16, w*16+16) across all 4 gates, all 32 rows.
    // lane: 8 rows (4 pairs) x 2 j x 4 gates -> acc[4][4][2] f32x2
    const int r0B = (lane & 3) * 8;
    const int cgB = lane >> 2;
    const int j0  = w * 16 + cgB * 2;

    u64 acc[4][4][2] = {};
    #pragma unroll 1
    for (int kc = 0; kc < 64; kc++) {
        int cur = kc & 1;
        if (kc < 63) {
            *(float4*)&sW[cur ^ 1][tid * 8] =
                *(const float4*)&g_W2[(kc + 1) * 2048 + tid * 8];
            *(float4*)&sW[cur ^ 1][tid * 8 + 4] =
                *(const float4*)&g_W2[(kc + 1) * 2048 + tid * 8 + 4];
        }
        const int sw = (kc & 7) << 2;          // ((k>>2)&7)<<2, k = kc*4+kk
        const int q0 = r0B ^ sw, q1 = q0 ^ 4;
        #pragma unroll
        for (int kk = 0; kk < 4; kk++) {
            const float* xk = &sXT[(kc * 4 + kk) * 32];
            ulonglong2 aA = *(ulonglong2*)&xk[q0];   // rows r0B..r0B+3 (2 pairs)
            ulonglong2 aB = *(ulonglong2*)&xk[q1];   // rows r0B+4..r0B+7
            #pragma unroll
            for (int g = 0; g < 4; g++) {
                float2 wv = *(float2*)&sW[cur][kk * 512 + g * 128 + j0];
                u64 w0 = pk2(wv.x), w1 = pk2(wv.y);
                ffma2(acc[0][g][0], aA.x, w0); ffma2(acc[0][g][1], aA.x, w1);
                ffma2(acc[1][g][0], aA.y, w0); ffma2(acc[1][g][1], aA.y, w1);
                ffma2(acc[2][g][0], aB.x, w0); ffma2(acc[2][g][1], aB.x, w1);
                ffma2(acc[3][g][0], aB.y, w0); ffma2(acc[3][g][1], aB.y, w1);
            }
        }
        __syncthreads();
    }

    // prefetch Wout chunk 0 (hidden by B2)
    *(float4*)&sW[0][tid * 8]     = *(const float4*)&Wout[tid * 8];
    *(float4*)&sW[0][tid * 8 + 4] = *(const float4*)&Wout[tid * 8 + 4];

    // ---------------- Phase B2: LSTM elementwise -------------------------
    // lane owns rows r0B..r0B+7 (pairs) x cols {j0, j0+1} of each gate.
    #pragma unroll
    for (int p = 0; p < 4; p++) {
        float2 u[4][2];
        #pragma unroll
        for (int g = 0; g < 4; g++) {
            u[g][0] = up2(acc[p][g][0]);
            u[g][1] = up2(acc[p][g][1]);
        }
        int rbase = r0B + 2 * p;
        float h2[2][2];
        #pragma unroll
        for (int rr = 0; rr < 2; rr++) {
            size_t gn = (size_t)(nodeBase + rbase + rr);
            float2 Ci = *(const float2*)&g_C[gn * 512 +   0 + j0];
            float2 Cf = *(const float2*)&g_C[gn * 512 + 128 + j0];
            float2 Cg = *(const float2*)&g_C[gn * 512 + 256 + j0];
            float2 Co = *(const float2*)&g_C[gn * 512 + 384 + j0];
            float2 cold = *(const float2*)&g_c[gn * 128 + j0];
            float cn[2];
            #pragma unroll
            for (int j = 0; j < 2; j++) {
                float pi = rr ? u[0][j].y : u[0][j].x;
                float pf = rr ? u[1][j].y : u[1][j].x;
                float pg = rr ? u[2][j].y : u[2][j].x;
                float po = rr ? u[3][j].y : u[3][j].x;
                float ig = sigm  (pi + (j ? Ci.y : Ci.x));
                float fg = sigm  (pf + (j ? Cf.y : Cf.x));
                float gg = tanhf_(pg + (j ? Cg.y : Cg.x));
                float og = sigm  (po + (j ? Co.y : Co.x));
                float cc = fg * (j ? cold.y : cold.x) + ig * gg;
                cn[j] = cc;
                h2[rr][j] = og * tanhf_(cc);
            }
            *(float2*)&g_c[gn * 128 + j0] = make_float2(cn[0], cn[1]);
            *(float2*)&hw [gn * 128 + j0] = make_float2(h2[rr][0], h2[rr][1]);
        }
        // stage h_t transposed into sXT (rows 0..127 = feature j), swizzled
        #pragma unroll
        for (int j = 0; j < 2; j++) {
            int jj = j0 + j;
            int swj = ((jj >> 2) & 7) << 2;
            *(float2*)&sXT[jj * 32 + (rbase ^ swj)] = make_float2(h2[0][j], h2[1][j]);
        }
    }

    // ---------------- Phase B3: output GEMM ------------------------------
    // warp: 32 rows x 8 cols; lane: 8 rows (4 pairs) x 1 col
    const int col = w * 8 + cgB;
    u64 oa[4] = {};
    #pragma unroll 1
    for (int ch = 0; ch < 4; ch++) {
        __syncthreads();             // chunk ch stores + (ch==0) sHT stores visible
        if (ch < 3) {
            *(float4*)&sW[(ch + 1) & 1][tid * 8] =
                *(const float4*)&Wout[(ch + 1) * 2048 + tid * 8];
            *(float4*)&sW[(ch + 1) & 1][tid * 8 + 4] =
                *(const float4*)&Wout[(ch + 1) * 2048 + tid * 8 + 4];
        }
        const float* wb = sW[ch & 1];
        #pragma unroll
        for (int k = 0; k < 32; k++) {
            int kg = ch * 32 + k;
            const int sw = ((k >> 2) & 7) << 2;   // (kg>>2)&7 == (k>>2)&7 (ch*8 ≡ 0 mod 8)
            const int q0 = r0B ^ sw, q1 = q0 ^ 4;
            ulonglong2 aA = *(ulonglong2*)&sXT[kg * 32 + q0];
            ulonglong2 aB = *(ulonglong2*)&sXT[kg * 32 + q1];
            u64 wd = pk2(wb[k * 64 + col]);
            ffma2(oa[0], aA.x, wd); ffma2(oa[1], aA.y, wd);
            ffma2(oa[2], aB.x, wd); ffma2(oa[3], aB.y, wd);
        }
    }
    float bo = bout[col];
    #pragma unroll
    for (int p = 0; p < 4; p++) {
        float2 hv = up2(oa[p]);
        size_t gn0 = (size_t)(nodeBase + r0B + 2 * p);
        size_t o0 = (gn0 * TT + t) * NINF + col;
        size_t o1 = ((gn0 + 1) * TT + t) * NINF + col;
        out[o0] = out[o0 - NINF] + hv.x + bo;
        out[o1] = out[o1 - NINF] + hv.y + bo;
    }
}

// ---------------- launch -----------------------------------------------------

extern "C" void kernel_launch(void* const* d_in, const int* in_sizes, int n_in,
                              void* d_out, int out_size) {
    (void)in_sizes; (void)n_in; (void)out_size;
    const float* X    = (const float*)d_in[0];
    const float* A    = (const float*)d_in[1];
    const float* Wse  = (const float*)d_in[2];
    const float* bse  = (const float*)d_in[3];
    const float* Wpe  = (const float*)d_in[4];
    const float* bpe  = (const float*)d_in[5];
    const float* Wii  = (const float*)d_in[6];
    const float* bii  = (const float*)d_in[7];
    const float* Whi  = (const float*)d_in[8];
    const float* bhi  = (const float*)d_in[9];
    const float* Wif  = (const float*)d_in[10];
    const float* bif  = (const float*)d_in[11];
    const float* Whf  = (const float*)d_in[12];
    const float* bhf  = (const float*)d_in[13];
    const float* Wig  = (const float*)d_in[14];
    const float* bgg  = (const float*)d_in[15];
    const float* Whg  = (const float*)d_in[16];
    const float* bhg  = (const float*)d_in[17];
    const float* Wio  = (const float*)d_in[18];
    const float* bio  = (const float*)d_in[19];
    const float* Who  = (const float*)d_in[20];
    const float* bho  = (const float*)d_in[21];
    const float* Wout = (const float*)d_in[22];
    const float* bout = (const float*)d_in[23];
    float* out = (float*)d_out;

    k_deg <<<512,  256>>>(A);
    k_norm<<<2048, 256>>>(A);
    k_w2  <<<128,  256>>>(Wpe, Wii, Wif, Wig, Wio, Whi, Whf, Whg, Who);
    k_cb  <<<1,    512>>>(bpe, Wii, Wif, Wig, Wio,
                          bii, bif, bgg, bio, bhi, bhf, bhg, bho);
    k_node<<<4096, 128>>>(X, Wse, bse, Wii, Wif, Wig, Wio, out);

    for (int t = 1; t < TT; t++) {
        k_fused<<<128, 256>>>(Wout, bout, out, t);
    }
}

// round 11
// speedup vs baseline: 1.1270x; 1.0135x over previous
#include <cuda_runtime.h>

#define BB   8
#define NN   512
#define TT   64
#define NINF 64
#define NH   128
#define NODES (BB*NN)   // 4096
#define HNELEM (NODES*NH)

// ---------------- scratch (device globals; no allocation allowed) ----------
__device__ float g_An[BB*NN*NN];      // normalized adjacency, 8.4 MB
__device__ float g_W2[256*512];       // [Wcomb(128x512) ; Whcomb(128x512)]
__device__ float g_cb[512];           // per-gate constant bias
__device__ float g_C[NODES*512];      // per-node constant gate term, 8.4 MB
__device__ float g_hpp[2*HNELEM];     // double-buffered hidden state
__device__ unsigned g_bar[BB*TT];     // per-batch per-step arrival counters

typedef unsigned long long u64;

__device__ __forceinline__ u64 pk2(float x) {
    u64 r; asm("mov.b64 %0, {%1,%1};" : "=l"(r) : "f"(x)); return r;
}
__device__ __forceinline__ void ffma2(u64 &d, u64 a, u64 b) {
    asm("fma.rn.f32x2 %0, %1, %2, %0;" : "+l"(d) : "l"(a), "l"(b));
}
__device__ __forceinline__ float2 up2(u64 v) {
    float2 r; asm("mov.b64 {%0, %1}, %2;" : "=f"(r.x), "=f"(r.y) : "l"(v)); return r;
}

__device__ __forceinline__ float sigm(float x)  { return 1.0f / (1.0f + __expf(-x)); }
__device__ __forceinline__ float tanhf_(float x){ return 2.0f / (1.0f + __expf(-2.0f*x)) - 1.0f; }

// ---------------- setup kernel 1: degrees + normalize + zero barriers -------
// grid 8 (one block per batch), block 1024
__global__ void __launch_bounds__(1024) k_degnorm(const float* __restrict__ A) {
    __shared__ float sdinv[NN];
    int b = blockIdx.x, tid = threadIdx.x;
    int wid = tid >> 5, lane = tid & 31;
    const float* Ab = A + (size_t)b * NN * NN;
    #pragma unroll 1
    for (int rr = 0; rr < 16; rr++) {
        int row = wid * 16 + rr;
        float s = 0.f;
        #pragma unroll
        for (int m = lane; m < NN; m += 32) s += Ab[row * NN + m];
        #pragma unroll
        for (int o = 16; o; o >>= 1) s += __shfl_down_sync(0xffffffffu, s, o);
        if (lane == 0) sdinv[row] = (s > 0.f) ? rsqrtf(s) : 0.f;
    }
    if (tid < TT) g_bar[b * TT + tid] = 0u;
    __syncthreads();
    const float4* A4 = (const float4*)Ab;
    float4* An4 = (float4*)(g_An + (size_t)b * NN * NN);
    #pragma unroll 1
    for (int i = 0; i < 64; i++) {
        int idx = tid + i * 1024;            // float4 index within batch
        int row = idx >> 7, m4 = idx & 127;
        float di = sdinv[row];
        float4 a = A4[idx];
        const float* dj = sdinv + m4 * 4;
        float4 r;
        r.x = a.x * di * dj[0];
        r.y = a.y * di * dj[1];
        r.z = a.z * di * dj[2];
        r.w = a.w * di * dj[3];
        An4[idx] = r;
    }
}

// ---------------- setup kernel 2: W2 + cb -----------------------------------
// grid 128, block 256; block 0 additionally computes cb
__global__ void k_w2cb(const float* __restrict__ Wpe, const float* __restrict__ bpe,
                       const float* Wii, const float* Wif, const float* Wig, const float* Wio,
                       const float* Whi, const float* Whf, const float* Whg, const float* Who,
                       const float* bii, const float* bif, const float* bgg, const float* bio,
                       const float* bhi, const float* bhf, const float* bhg, const float* bho) {
    __shared__ float sp[128];
    int k = blockIdx.x;
    if (threadIdx.x < 128) sp[threadIdx.x] = Wpe[k * 128 + threadIdx.x];
    __syncthreads();
    for (int c = threadIdx.x; c < 512; c += blockDim.x) {
        int g = c >> 7, j = c & 127;
        const float* Wg = (g == 0) ? Wii : (g == 1) ? Wif : (g == 2) ? Wig : Wio;
        const float* Wh = (g == 0) ? Whi : (g == 1) ? Whf : (g == 2) ? Whg : Who;
        float s = 0.f;
        #pragma unroll 8
        for (int r = 0; r < 128; r++) s += sp[r] * Wg[(128 + r) * 128 + j];
        g_W2[k * 512 + c]         = s;
        g_W2[(128 + k) * 512 + c] = Wh[k * 128 + j];
    }
    if (blockIdx.x == 0) {
        for (int c = threadIdx.x; c < 512; c += blockDim.x) {
            int g = c >> 7, j = c & 127;
            const float* Wg = (g == 0) ? Wii : (g == 1) ? Wif : (g == 2) ? Wig : Wio;
            const float* bi = (g == 0) ? bii : (g == 1) ? bif : (g == 2) ? bgg : bio;
            const float* bh = (g == 0) ? bhi : (g == 1) ? bhf : (g == 2) ? bhg : bho;
            float s = bi[j] + bh[j];
            #pragma unroll 8
            for (int r = 0; r < 128; r++) s += bpe[r] * Wg[(128 + r) * 128 + j];
            g_cb[c] = s;
        }
    }
}

// ---------------- setup kernel 3: per-node constants + out[t=0] -------------
// grid 4096, block 128
__global__ void k_node(const float* __restrict__ X,
                       const float* __restrict__ Wse, const float* __restrict__ bse,
                       const float* Wii, const float* Wif, const float* Wig, const float* Wio,
                       float* __restrict__ out) {
    __shared__ float sx0[64];
    __shared__ float ses[128];
    int node = blockIdx.x;
    int j = threadIdx.x;
    size_t xbase = (size_t)node * TT * NINF;
    if (j < 64) { float v = X[xbase + j]; sx0[j] = v; out[xbase + j] = v; }
    __syncthreads();
    float e = bse[j];
    #pragma unroll 8
    for (int k = 0; k < 64; k++) e += sx0[k] * Wse[k * 128 + j];
    ses[j] = e;
    __syncthreads();
    #pragma unroll
    for (int g = 0; g < 4; g++) {
        const float* Wg = (g == 0) ? Wii : (g == 1) ? Wif : (g == 2) ? Wig : Wio;
        float s = g_cb[g * 128 + j];
        #pragma unroll 8
        for (int k = 0; k < 128; k++) s += ses[k] * Wg[k * 128 + j];
        g_C[(size_t)node * 512 + g * 128 + j] = s;
    }
}

// ---------------- persistent per-step kernel ---------------------------------
// grid 128 (= 8 batches x 16 row-tiles of 32), block 256, 1 block/SM, 63 steps.
__global__ void __launch_bounds__(256, 1) k_persist(const float* __restrict__ X,
                                                    const float* __restrict__ Wout,
                                                    const float* __restrict__ bout,
                                                    float* __restrict__ out) {
    __shared__ __align__(16) float smem[12288];   // 48 KB
    float* sXT = smem;                 // B phases: [k 0..255][r 0..31], XOR swizzle
    float* sW0 = smem + 8192;
    float* sW1 = smem + 10240;
    // Phase A double buffers: p*5120 (An^T 1024 floats) | +1024 (h tile 4096 floats)

    const int tid  = threadIdx.x;
    const int w    = tid >> 5;
    const int lane = tid & 31;
    const int b    = blockIdx.x >> 4;
    const int row0 = (blockIdx.x & 15) * 32;
    const int nodeBase = b * NN + row0;
    const float* An = g_An + (size_t)b * NN * NN;

    // Phase A lane mapping: 4 rows (2 pairs) x 4 feats per lane
    const int r0A = (lane & 7) * 4;
    const int fgA = lane >> 3;
    const int f0A = w * 16 + fgA * 4;
    const int kk4 = tid & 7;           // An loader: k-float4 index
    const int rL  = tid >> 3;          // An loader: row
    // Phase B lane mapping: 8 rows (4 pairs) x 2 j x 4 gates
    const int r0B = (lane & 3) * 8;
    const int cgB = lane >> 2;
    const int j0  = w * 16 + cgB * 2;
    const int colO = w * 8 + cgB;      // B3: one output col per lane

    // persistent register state: c and running output Xi
    float2 creg[4][2];
    #pragma unroll
    for (int p = 0; p < 4; p++) { creg[p][0] = make_float2(0.f, 0.f);
                                  creg[p][1] = make_float2(0.f, 0.f); }
    float Xi[8];
    #pragma unroll
    for (int p = 0; p < 4; p++)
        #pragma unroll
        for (int rr = 0; rr < 2; rr++)
            Xi[p * 2 + rr] = X[(size_t)(nodeBase + r0B + 2 * p + rr) * (TT * NINF) + colO];
    const float boutv = bout[colO];

    volatile unsigned* barv = (volatile unsigned*)g_bar;

    #pragma unroll 1
    for (int t = 1; t < TT; t++) {
        const float* hr = g_hpp + ((t - 1) & 1) * HNELEM;
        float*       hw = g_hpp + (t & 1)       * HNELEM;
        u64 acc[4][4][2] = {};

        if (t > 1) {
            if (tid == 0) { while (barv[b * TT + (t - 1)] < 16u) { } }
            __syncthreads();           // release block; also orders prev B3 sXT reads

            // ---------------- Phase A: H = An_tile @ h (double-buffered) ----
            u64 accA[2][4] = {};
            {   // preload kb = 0 into buffer 0
                float* sAT = smem; float* sB = smem + 1024;
                float4 v = *(const float4*)&An[(size_t)(row0 + rL) * NN + kk4 * 4];
                int rsw = rL ^ (kk4 << 2);
                sAT[(kk4 * 4 + 0) * 32 + rsw] = v.x;
                sAT[(kk4 * 4 + 1) * 32 + rsw] = v.y;
                sAT[(kk4 * 4 + 2) * 32 + rsw] = v.z;
                sAT[(kk4 * 4 + 3) * 32 + rsw] = v.w;
                #pragma unroll
                for (int p2 = 0; p2 < 4; p2++) {
                    int id = tid + p2 * 256;
                    int kL = id >> 5, f4 = id & 31;
                    float4 hv = __ldcg((const float4*)&hr[(size_t)(b * NN + kL) * NH + f4 * 4]);
                    *(float4*)&sB[kL * 128 + f4 * 4] = hv;
                }
            }
            __syncthreads();
            #pragma unroll 1
            for (int kb = 0; kb < 16; kb++) {
                if (kb < 15) {
                    float* sAT = smem + ((kb + 1) & 1) * 5120;
                    float* sB  = sAT + 1024;
                    float4 v = *(const float4*)&An[(size_t)(row0 + rL) * NN + (kb + 1) * 32 + kk4 * 4];
                    int rsw = rL ^ (kk4 << 2);
                    sAT[(kk4 * 4 + 0) * 32 + rsw] = v.x;
                    sAT[(kk4 * 4 + 1) * 32 + rsw] = v.y;
                    sAT[(kk4 * 4 + 2) * 32 + rsw] = v.z;
                    sAT[(kk4 * 4 + 3) * 32 + rsw] = v.w;
                    #pragma unroll
                    for (int p2 = 0; p2 < 4; p2++) {
                        int id = tid + p2 * 256;
                        int kL = id >> 5, f4 = id & 31;
                        float4 hv = __ldcg((const float4*)
                            &hr[(size_t)(b * NN + (kb + 1) * 32 + kL) * NH + f4 * 4]);
                        *(float4*)&sB[kL * 128 + f4 * 4] = hv;
                    }
                }
                const float* sAT = smem + (kb & 1) * 5120;
                const float* sB  = sAT + 1024;
                #pragma unroll
                for (int k = 0; k < 32; k++) {
                    const int sw = ((k >> 2) & 7) << 2;
                    ulonglong2 ap = *(ulonglong2*)&sAT[k * 32 + (r0A ^ sw)];
                    float4 bf = *(float4*)&sB[k * 128 + f0A];
                    u64 b0 = pk2(bf.x), b1 = pk2(bf.y), b2 = pk2(bf.z), b3 = pk2(bf.w);
                    ffma2(accA[0][0], ap.x, b0); ffma2(accA[0][1], ap.x, b1);
                    ffma2(accA[0][2], ap.x, b2); ffma2(accA[0][3], ap.x, b3);
                    ffma2(accA[1][0], ap.y, b0); ffma2(accA[1][1], ap.y, b1);
                    ffma2(accA[1][2], ap.y, b2); ffma2(accA[1][3], ap.y, b3);
                }
                __syncthreads();
            }

            // H -> sXT rows 0..127 (transposed, swizzled); own h -> rows 128..255
            {
                const int swH = ((w * 4 + fgA) & 7) << 2;
                #pragma unroll
                for (int ff = 0; ff < 4; ff++)
                    #pragma unroll
                    for (int p2 = 0; p2 < 2; p2++)
                        *(u64*)&sXT[(f0A + ff) * 32 + ((r0A + 2 * p2) ^ swH)] = accA[p2][ff];
            }
            #pragma unroll
            for (int p2 = 0; p2 < 4; p2++) {
                int id = tid + p2 * 256;
                int r = id & 31, f4 = id >> 5;
                float4 v = __ldcg((const float4*)&hr[(size_t)(nodeBase + r) * NH + f4 * 4]);
                int rsw = r ^ ((f4 & 7) << 2);
                sXT[(128 + f4 * 4 + 0) * 32 + rsw] = v.x;
                sXT[(128 + f4 * 4 + 1) * 32 + rsw] = v.y;
                sXT[(128 + f4 * 4 + 2) * 32 + rsw] = v.z;
                sXT[(128 + f4 * 4 + 3) * 32 + rsw] = v.w;
            }
            {   // prefetch W2 chunk 0 (.cg: keep L1 for An/C/Wout)
                float4 w0 = __ldcg((const float4*)&g_W2[tid * 8]);
                float4 w1 = __ldcg((const float4*)&g_W2[tid * 8 + 4]);
                *(float4*)&sW0[tid * 8] = w0; *(float4*)&sW0[tid * 8 + 4] = w1;
            }
            __syncthreads();

            // ---------------- Phase B1: gate GEMM ----------------------------
            #pragma unroll 1
            for (int kc = 0; kc < 64; kc++) {
                float* cw = (kc & 1) ? sW1 : sW0;
                if (kc < 63) {
                    float* nw = (kc & 1) ? sW0 : sW1;
                    float4 w0 = __ldcg((const float4*)&g_W2[(kc + 1) * 2048 + tid * 8]);
                    float4 w1 = __ldcg((const float4*)&g_W2[(kc + 1) * 2048 + tid * 8 + 4]);
                    *(float4*)&nw[tid * 8] = w0; *(float4*)&nw[tid * 8 + 4] = w1;
                }
                const int sw = (kc & 7) << 2;
                const int q0 = r0B ^ sw, q1 = q0 ^ 4;
                #pragma unroll
                for (int kk = 0; kk < 4; kk++) {
                    const float* xk = &sXT[(kc * 4 + kk) * 32];
                    ulonglong2 aA = *(ulonglong2*)&xk[q0];
                    ulonglong2 aB = *(ulonglong2*)&xk[q1];
                    #pragma unroll
                    for (int g = 0; g < 4; g++) {
                        float2 wv = *(float2*)&cw[kk * 512 + g * 128 + j0];
                        u64 w0 = pk2(wv.x), w1 = pk2(wv.y);
                        ffma2(acc[0][g][0], aA.x, w0); ffma2(acc[0][g][1], aA.x, w1);
                        ffma2(acc[1][g][0], aA.y, w0); ffma2(acc[1][g][1], aA.y, w1);
                        ffma2(acc[2][g][0], aB.x, w0); ffma2(acc[2][g][1], aB.x, w1);
                        ffma2(acc[3][g][0], aB.y, w0); ffma2(acc[3][g][1], aB.y, w1);
                    }
                }
                __syncthreads();
            }
        } else {
            __syncthreads();
        }

        // ---------------- Phase B2: LSTM elementwise (c in registers) --------
        #pragma unroll
        for (int p = 0; p < 4; p++) {
            float2 u[4][2];
            #pragma unroll
            for (int g = 0; g < 4; g++) {
                u[g][0] = up2(acc[p][g][0]);
                u[g][1] = up2(acc[p][g][1]);
            }
            int rbase = r0B + 2 * p;
            float h2[2][2];
            #pragma unroll
            for (int rr = 0; rr < 2; rr++) {
                size_t gn = (size_t)(nodeBase + rbase + rr);
                float2 Ci = *(const float2*)&g_C[gn * 512 +   0 + j0];
                float2 Cf = *(const float2*)&g_C[gn * 512 + 128 + j0];
                float2 Cg = *(const float2*)&g_C[gn * 512 + 256 + j0];
                float2 Co = *(const float2*)&g_C[gn * 512 + 384 + j0];
                float2 cold = creg[p][rr];
                float cn[2];
                #pragma unroll
                for (int j = 0; j < 2; j++) {
                    float pi = rr ? u[0][j].y : u[0][j].x;
                    float pf = rr ? u[1][j].y : u[1][j].x;
                    float pg = rr ? u[2][j].y : u[2][j].x;
                    float po = rr ? u[3][j].y : u[3][j].x;
                    float ig = sigm  (pi + (j ? Ci.y : Ci.x));
                    float fg = sigm  (pf + (j ? Cf.y : Cf.x));
                    float gg = tanhf_(pg + (j ? Cg.y : Cg.x));
                    float og = sigm  (po + (j ? Co.y : Co.x));
                    float cc = fg * (j ? cold.y : cold.x) + ig * gg;
                    cn[j] = cc;
                    h2[rr][j] = og * tanhf_(cc);
                }
                creg[p][rr] = make_float2(cn[0], cn[1]);
                __stcg((float2*)&hw[gn * 128 + j0], make_float2(h2[rr][0], h2[rr][1]));
            }
            #pragma unroll
            for (int j = 0; j < 2; j++) {
                int jj = j0 + j;
                int swj = ((jj >> 2) & 7) << 2;
                *(float2*)&sXT[jj * 32 + (rbase ^ swj)] = make_float2(h2[0][j], h2[1][j]);
            }
        }
        __threadfence();               // h^t visible before arrival signal
        {   // prefetch Wout chunk 0 (L1-resident after first step)
            float4 w0 = *(const float4*)&Wout[tid * 8];
            float4 w1 = *(const float4*)&Wout[tid * 8 + 4];
            *(float4*)&sW0[tid * 8] = w0; *(float4*)&sW0[tid * 8 + 4] = w1;
        }
        __syncthreads();               // all fences done; h_t staging visible
        if (tid == 0) atomicAdd(&g_bar[b * TT + t], 1u);

        // ---------------- Phase B3: output GEMM, Xi in registers -------------
        u64 oa[4] = {};
        #pragma unroll 1
        for (int ch = 0; ch < 4; ch++) {
            const float* cw = (ch & 1) ? sW1 : sW0;
            if (ch < 3) {
                float* nw = (ch & 1) ? sW0 : sW1;
                float4 w0 = *(const float4*)&Wout[(ch + 1) * 2048 + tid * 8];
                float4 w1 = *(const float4*)&Wout[(ch + 1) * 2048 + tid * 8 + 4];
                *(float4*)&nw[tid * 8] = w0; *(float4*)&nw[tid * 8 + 4] = w1;
            }
            #pragma unroll
            for (int k = 0; k < 32; k++) {
                int kg = ch * 32 + k;
                const int sw = ((k >> 2) & 7) << 2;
                const int q0 = r0B ^ sw, q1 = q0 ^ 4;
                ulonglong2 aA = *(ulonglong2*)&sXT[kg * 32 + q0];
                ulonglong2 aB = *(ulonglong2*)&sXT[kg * 32 + q1];
                u64 wd = pk2(cw[k * 64 + colO]);
                ffma2(oa[0], aA.x, wd); ffma2(oa[1], aA.y, wd);
                ffma2(oa[2], aB.x, wd); ffma2(oa[3], aB.y, wd);
            }
            __syncthreads();
        }
        #pragma unroll
        for (int p = 0; p < 4; p++) {
            float2 hv = up2(oa[p]);
            Xi[p * 2 + 0] += hv.x + boutv;
            Xi[p * 2 + 1] += hv.y + boutv;
            size_t gn0 = (size_t)(nodeBase + r0B + 2 * p);
            out[(gn0 * TT + t) * NINF + colO]       = Xi[p * 2 + 0];
            out[((gn0 + 1) * TT + t) * NINF + colO] = Xi[p * 2 + 1];
        }
    }
}

// ---------------- launch -----------------------------------------------------

extern "C" void kernel_launch(void* const* d_in, const int* in_sizes, int n_in,
                              void* d_out, int out_size) {
    (void)in_sizes; (void)n_in; (void)out_size;
    const float* X    = (const float*)d_in[0];
    const float* A    = (const float*)d_in[1];
    const float* Wse  = (const float*)d_in[2];
    const float* bse  = (const float*)d_in[3];
    const float* Wpe  = (const float*)d_in[4];
    const float* bpe  = (const float*)d_in[5];
    const float* Wii  = (const float*)d_in[6];
    const float* bii  = (const float*)d_in[7];
    const float* Whi  = (const float*)d_in[8];
    const float* bhi  = (const float*)d_in[9];
    const float* Wif  = (const float*)d_in[10];
    const float* bif  = (const float*)d_in[11];
    const float* Whf  = (const float*)d_in[12];
    const float* bhf  = (const float*)d_in[13];
    const float* Wig  = (const float*)d_in[14];
    const float* bgg  = (const float*)d_in[15];
    const float* Whg  = (const float*)d_in[16];
    const float* bhg  = (const float*)d_in[17];
    const float* Wio  = (const float*)d_in[18];
    const float* bio  = (const float*)d_in[19];
    const float* Who  = (const float*)d_in[20];
    const float* bho  = (const float*)d_in[21];
    const float* Wout = (const float*)d_in[22];
    const float* bout = (const float*)d_in[23];
    float* out = (float*)d_out;

    k_degnorm<<<8, 1024>>>(A);
    k_w2cb<<<128, 256>>>(Wpe, bpe, Wii, Wif, Wig, Wio, Whi, Whf, Whg, Who,
                         bii, bif, bgg, bio, bhi, bhf, bhg, bho);
    k_node<<<4096, 128>>>(X, Wse, bse, Wii, Wif, Wig, Wio, out);
    k_persist<<<128, 256>>>(X, Wout, bout, out);
}

// round 12
// speedup vs baseline: 1.2712x; 1.1280x over previous
#include <cuda_runtime.h>

#define BB   8
#define NN   512
#define TT   64
#define NINF 64
#define NH   128
#define NODES (BB*NN)   // 4096
#define HNELEM (NODES*NH)

// ---------------- scratch (device globals; no allocation allowed) ----------
__device__ float g_An[BB*NN*NN];      // normalized adjacency, 8.4 MB
__device__ float g_W2[256*512];       // [Wcomb(128x512) ; Whcomb(128x512)]
__device__ float g_cb[512];           // per-gate constant bias
__device__ float g_C[NODES*512];      // per-node constant gate term, 8.4 MB
__device__ float g_hpp[2*HNELEM];     // double-buffered hidden state
__device__ unsigned g_bar[BB*TT];     // per-batch per-step arrival counters

typedef unsigned long long u64;

__device__ __forceinline__ u64 pk2(float x) {
    u64 r; asm("mov.b64 %0, {%1,%1};" : "=l"(r) : "f"(x)); return r;
}
__device__ __forceinline__ void ffma2(u64 &d, u64 a, u64 b) {
    asm("fma.rn.f32x2 %0, %1, %2, %0;" : "+l"(d) : "l"(a), "l"(b));
}
__device__ __forceinline__ float2 up2(u64 v) {
    float2 r; asm("mov.b64 {%0, %1}, %2;" : "=f"(r.x), "=f"(r.y) : "l"(v)); return r;
}

__device__ __forceinline__ float sigm(float x)  { return 1.0f / (1.0f + __expf(-x)); }
__device__ __forceinline__ float tanhf_(float x){ return 2.0f / (1.0f + __expf(-2.0f*x)) - 1.0f; }

// ---------------- setup kernel 1: degrees + normalize + zero barriers -------
__global__ void __launch_bounds__(1024) k_degnorm(const float* __restrict__ A) {
    __shared__ float sdinv[NN];
    int b = blockIdx.x, tid = threadIdx.x;
    int wid = tid >> 5, lane = tid & 31;
    const float* Ab = A + (size_t)b * NN * NN;
    #pragma unroll 1
    for (int rr = 0; rr < 16; rr++) {
        int row = wid * 16 + rr;
        float s = 0.f;
        #pragma unroll
        for (int m = lane; m < NN; m += 32) s += Ab[row * NN + m];
        #pragma unroll
        for (int o = 16; o; o >>= 1) s += __shfl_down_sync(0xffffffffu, s, o);
        if (lane == 0) sdinv[row] = (s > 0.f) ? rsqrtf(s) : 0.f;
    }
    if (tid < TT) g_bar[b * TT + tid] = 0u;
    __syncthreads();
    const float4* A4 = (const float4*)Ab;
    float4* An4 = (float4*)(g_An + (size_t)b * NN * NN);
    #pragma unroll 1
    for (int i = 0; i < 64; i++) {
        int idx = tid + i * 1024;
        int row = idx >> 7, m4 = idx & 127;
        float di = sdinv[row];
        float4 a = A4[idx];
        const float* dj = sdinv + m4 * 4;
        float4 r;
        r.x = a.x * di * dj[0];
        r.y = a.y * di * dj[1];
        r.z = a.z * di * dj[2];
        r.w = a.w * di * dj[3];
        An4[idx] = r;
    }
}

// ---------------- setup kernel 2: W2 + cb -----------------------------------
__global__ void k_w2cb(const float* __restrict__ Wpe, const float* __restrict__ bpe,
                       const float* Wii, const float* Wif, const float* Wig, const float* Wio,
                       const float* Whi, const float* Whf, const float* Whg, const float* Who,
                       const float* bii, const float* bif, const float* bgg, const float* bio,
                       const float* bhi, const float* bhf, const float* bhg, const float* bho) {
    __shared__ float sp[128];
    int k = blockIdx.x;
    if (threadIdx.x < 128) sp[threadIdx.x] = Wpe[k * 128 + threadIdx.x];
    __syncthreads();
    for (int c = threadIdx.x; c < 512; c += blockDim.x) {
        int g = c >> 7, j = c & 127;
        const float* Wg = (g == 0) ? Wii : (g == 1) ? Wif : (g == 2) ? Wig : Wio;
        const float* Wh = (g == 0) ? Whi : (g == 1) ? Whf : (g == 2) ? Whg : Who;
        float s = 0.f;
        #pragma unroll 8
        for (int r = 0; r < 128; r++) s += sp[r] * Wg[(128 + r) * 128 + j];
        g_W2[k * 512 + c]         = s;
        g_W2[(128 + k) * 512 + c] = Wh[k * 128 + j];
    }
    if (blockIdx.x == 0) {
        for (int c = threadIdx.x; c < 512; c += blockDim.x) {
            int g = c >> 7, j = c & 127;
            const float* Wg = (g == 0) ? Wii : (g == 1) ? Wif : (g == 2) ? Wig : Wio;
            const float* bi = (g == 0) ? bii : (g == 1) ? bif : (g == 2) ? bgg : bio;
            const float* bh = (g == 0) ? bhi : (g == 1) ? bhf : (g == 2) ? bhg : bho;
            float s = bi[j] + bh[j];
            #pragma unroll 8
            for (int r = 0; r < 128; r++) s += bpe[r] * Wg[(128 + r) * 128 + j];
            g_cb[c] = s;
        }
    }
}

// ---------------- setup kernel 3: per-node constants + out[t=0] -------------
__global__ void k_node(const float* __restrict__ X,
                       const float* __restrict__ Wse, const float* __restrict__ bse,
                       const float* Wii, const float* Wif, const float* Wig, const float* Wio,
                       float* __restrict__ out) {
    __shared__ float sx0[64];
    __shared__ float ses[128];
    int node = blockIdx.x;
    int j = threadIdx.x;
    size_t xbase = (size_t)node * TT * NINF;
    if (j < 64) { float v = X[xbase + j]; sx0[j] = v; out[xbase + j] = v; }
    __syncthreads();
    float e = bse[j];
    #pragma unroll 8
    for (int k = 0; k < 64; k++) e += sx0[k] * Wse[k * 128 + j];
    ses[j] = e;
    __syncthreads();
    #pragma unroll
    for (int g = 0; g < 4; g++) {
        const float* Wg = (g == 0) ? Wii : (g == 1) ? Wif : (g == 2) ? Wig : Wio;
        float s = g_cb[g * 128 + j];
        #pragma unroll 8
        for (int k = 0; k < 128; k++) s += ses[k] * Wg[k * 128 + j];
        g_C[(size_t)node * 512 + g * 128 + j] = s;
    }
}

// ---------------- persistent per-step kernel ---------------------------------
// grid 128 (= 8 batches x 16 row-tiles of 32), block 512 (16 warps), 63 steps.
// Warps 0-7: Phase A compute.  Warps 8-15: Phase A producers (An/h -> SMEM).
__global__ void __launch_bounds__(512, 1) k_persist(const float* __restrict__ X,
                                                    const float* __restrict__ Wout,
                                                    const float* __restrict__ bout,
                                                    float* __restrict__ out) {
    __shared__ __align__(16) float smem[12288];   // 48 KB
    float* sXT = smem;                 // B phases: [k 0..255][r 0..31], XOR swizzle
    float* sW0 = smem + 8192;
    float* sW1 = smem + 10240;
    // Phase A double buffers at p*5120: An^T (1024 floats) | h tile (4096 floats)

    const int tid  = threadIdx.x;
    const int w    = tid >> 5;
    const int lane = tid & 31;
    const int b    = blockIdx.x >> 4;
    const int row0 = (blockIdx.x & 15) * 32;
    const int nodeBase = b * NN + row0;
    const float* An = g_An + (size_t)b * NN * NN;

    // Phase A compute mapping (warps 0-7): 4 rows (2 pairs) x 4 feats per lane
    const int r0A = (lane & 7) * 4;
    const int fgA = lane >> 3;
    const int f0A = w * 16 + fgA * 4;          // valid for w<8
    // Phase A producer mapping (warps 8-15)
    const int ptid = tid - 256;                // 0..255 for producers
    const int kk4  = ptid & 7;
    const int rL   = ptid >> 3;
    // Phase B1/B2 mapping: 4 rows (2 pairs) x 2 j x 4 gates per lane
    const int r0B = (lane & 7) * 4;
    const int jg  = lane >> 3;                 // 0..3
    const int j0  = w * 8 + jg * 2;            // 0..126, even
    // Phase B3 mapping: 4 rows x 1 col per lane
    const int r0O  = (lane & 7) * 4;
    const int colO = w * 4 + (lane >> 3);      // 0..63

    // persistent register state: c and running output Xi
    float2 creg[2][2];
    #pragma unroll
    for (int p = 0; p < 2; p++) { creg[p][0] = make_float2(0.f, 0.f);
                                  creg[p][1] = make_float2(0.f, 0.f); }
    float Xi[4];
    #pragma unroll
    for (int q = 0; q < 4; q++)
        Xi[q] = X[(size_t)(nodeBase + r0O + q) * (TT * NINF) + colO];
    const float boutv = bout[colO];

    volatile unsigned* barv = (volatile unsigned*)g_bar;

    #pragma unroll 1
    for (int t = 1; t < TT; t++) {
        const float* hr = g_hpp + ((t - 1) & 1) * HNELEM;
        float*       hw = g_hpp + (t & 1)       * HNELEM;
        u64 acc[2][4][2] = {};

        if (t > 1) {
            // producers preload An kb=0 (independent of h) while tid0 spins
            if (w >= 8) {
                float* sAT = smem;
                float4 v = *(const float4*)&An[(size_t)(row0 + rL) * NN + kk4 * 4];
                int rsw = rL ^ (kk4 << 2);
                sAT[(kk4 * 4 + 0) * 32 + rsw] = v.x;
                sAT[(kk4 * 4 + 1) * 32 + rsw] = v.y;
                sAT[(kk4 * 4 + 2) * 32 + rsw] = v.z;
                sAT[(kk4 * 4 + 3) * 32 + rsw] = v.w;
            }
            if (tid == 0) { while (barv[b * TT + (t - 1)] < 16u) { } }
            __syncthreads();           // h^{t-1} visible to whole block

            if (w >= 8) {              // h tile kb=0
                float* sB = smem + 1024;
                #pragma unroll
                for (int p2 = 0; p2 < 4; p2++) {
                    int id = ptid + p2 * 256;
                    int kL = id >> 5, f4 = id & 31;
                    float4 hv = __ldcg((const float4*)&hr[(size_t)(b * NN + kL) * NH + f4 * 4]);
                    *(float4*)&sB[kL * 128 + f4 * 4] = hv;
                }
            }
            __syncthreads();

            // ---------------- Phase A: H = An_tile @ h (producer/consumer) --
            u64 accA[2][4] = {};
            #pragma unroll 1
            for (int kb = 0; kb < 16; kb++) {
                if (w >= 8) {
                    if (kb < 15) {
                        float* sAT = smem + ((kb + 1) & 1) * 5120;
                        float* sB  = sAT + 1024;
                        float4 v = *(const float4*)
                            &An[(size_t)(row0 + rL) * NN + (kb + 1) * 32 + kk4 * 4];
                        int rsw = rL ^ (kk4 << 2);
                        sAT[(kk4 * 4 + 0) * 32 + rsw] = v.x;
                        sAT[(kk4 * 4 + 1) * 32 + rsw] = v.y;
                        sAT[(kk4 * 4 + 2) * 32 + rsw] = v.z;
                        sAT[(kk4 * 4 + 3) * 32 + rsw] = v.w;
                        #pragma unroll
                        for (int p2 = 0; p2 < 4; p2++) {
                            int id = ptid + p2 * 256;
                            int kL = id >> 5, f4 = id & 31;
                            float4 hv = __ldcg((const float4*)
                                &hr[(size_t)(b * NN + (kb + 1) * 32 + kL) * NH + f4 * 4]);
                            *(float4*)&sB[kL * 128 + f4 * 4] = hv;
                        }
                    }
                } else {
                    const float* sAT = smem + (kb & 1) * 5120;
                    const float* sB  = sAT + 1024;
                    #pragma unroll
                    for (int k = 0; k < 32; k++) {
                        const int sw = ((k >> 2) & 7) << 2;
                        ulonglong2 ap = *(ulonglong2*)&sAT[k * 32 + (r0A ^ sw)];
                        float4 bf = *(float4*)&sB[k * 128 + f0A];
                        u64 b0 = pk2(bf.x), b1 = pk2(bf.y), b2 = pk2(bf.z), b3 = pk2(bf.w);
                        ffma2(accA[0][0], ap.x, b0); ffma2(accA[0][1], ap.x, b1);
                        ffma2(accA[0][2], ap.x, b2); ffma2(accA[0][3], ap.x, b3);
                        ffma2(accA[1][0], ap.y, b0); ffma2(accA[1][1], ap.y, b1);
                        ffma2(accA[1][2], ap.y, b2); ffma2(accA[1][3], ap.y, b3);
                    }
                }
                __syncthreads();
            }

            // H -> sXT rows 0..127 (transposed, swizzled) by warps 0-7
            if (w < 8) {
                const int swH = ((w * 4 + fgA) & 7) << 2;
                #pragma unroll
                for (int ff = 0; ff < 4; ff++)
                    #pragma unroll
                    for (int p2 = 0; p2 < 2; p2++)
                        *(u64*)&sXT[(f0A + ff) * 32 + ((r0A + 2 * p2) ^ swH)] = accA[p2][ff];
            }
            // own h tile -> rows 128..255 (all threads, 2 float4 each)
            #pragma unroll
            for (int p2 = 0; p2 < 2; p2++) {
                int id = tid + p2 * 512;
                int r = id & 31, f4 = id >> 5;
                float4 v = __ldcg((const float4*)&hr[(size_t)(nodeBase + r) * NH + f4 * 4]);
                int rsw = r ^ ((f4 & 7) << 2);
                sXT[(128 + f4 * 4 + 0) * 32 + rsw] = v.x;
                sXT[(128 + f4 * 4 + 1) * 32 + rsw] = v.y;
                sXT[(128 + f4 * 4 + 2) * 32 + rsw] = v.z;
                sXT[(128 + f4 * 4 + 3) * 32 + rsw] = v.w;
            }
            {   // prefetch W2 chunk 0
                float4 wv = __ldcg((const float4*)&g_W2[tid * 4]);
                *(float4*)&sW0[tid * 4] = wv;
            }
            __syncthreads();

            // ---------------- Phase B1: gate GEMM ----------------------------
            #pragma unroll 1
            for (int kc = 0; kc < 64; kc++) {
                float* cw = (kc & 1) ? sW1 : sW0;
                if (kc < 63) {
                    float* nw = (kc & 1) ? sW0 : sW1;
                    float4 wv = __ldcg((const float4*)&g_W2[(kc + 1) * 2048 + tid * 4]);
                    *(float4*)&nw[tid * 4] = wv;
                }
                const int sw = (kc & 7) << 2;
                const int q0 = r0B ^ sw;
                #pragma unroll
                for (int kk = 0; kk < 4; kk++) {
                    const float* xk = &sXT[(kc * 4 + kk) * 32];
                    ulonglong2 aA = *(ulonglong2*)&xk[q0];   // rows r0B..r0B+3
                    #pragma unroll
                    for (int g = 0; g < 4; g++) {
                        float2 wv = *(float2*)&cw[kk * 512 + g * 128 + j0];
                        u64 w0 = pk2(wv.x), w1 = pk2(wv.y);
                        ffma2(acc[0][g][0], aA.x, w0); ffma2(acc[0][g][1], aA.x, w1);
                        ffma2(acc[1][g][0], aA.y, w0); ffma2(acc[1][g][1], aA.y, w1);
                    }
                }
                __syncthreads();
            }
        } else {
            __syncthreads();
        }

        // ---------------- Phase B2: LSTM elementwise (c in registers) --------
        #pragma unroll
        for (int p = 0; p < 2; p++) {
            float2 u[4][2];
            #pragma unroll
            for (int g = 0; g < 4; g++) {
                u[g][0] = up2(acc[p][g][0]);
                u[g][1] = up2(acc[p][g][1]);
            }
            int rbase = r0B + 2 * p;
            float h2[2][2];
            #pragma unroll
            for (int rr = 0; rr < 2; rr++) {
                size_t gn = (size_t)(nodeBase + rbase + rr);
                float2 Ci = *(const float2*)&g_C[gn * 512 +   0 + j0];
                float2 Cf = *(const float2*)&g_C[gn * 512 + 128 + j0];
                float2 Cg = *(const float2*)&g_C[gn * 512 + 256 + j0];
                float2 Co = *(const float2*)&g_C[gn * 512 + 384 + j0];
                float2 cold = creg[p][rr];
                float cn[2];
                #pragma unroll
                for (int j = 0; j < 2; j++) {
                    float pi = rr ? u[0][j].y : u[0][j].x;
                    float pf = rr ? u[1][j].y : u[1][j].x;
                    float pg = rr ? u[2][j].y : u[2][j].x;
                    float po = rr ? u[3][j].y : u[3][j].x;
                    float ig = sigm  (pi + (j ? Ci.y : Ci.x));
                    float fg = sigm  (pf + (j ? Cf.y : Cf.x));
                    float gg = tanhf_(pg + (j ? Cg.y : Cg.x));
                    float og = sigm  (po + (j ? Co.y : Co.x));
                    float cc = fg * (j ? cold.y : cold.x) + ig * gg;
                    cn[j] = cc;
                    h2[rr][j] = og * tanhf_(cc);
                }
                creg[p][rr] = make_float2(cn[0], cn[1]);
                __stcg((float2*)&hw[gn * 128 + j0], make_float2(h2[rr][0], h2[rr][1]));
            }
            #pragma unroll
            for (int j = 0; j < 2; j++) {
                int jj = j0 + j;
                int swj = ((jj >> 2) & 7) << 2;
                *(float2*)&sXT[jj * 32 + (rbase ^ swj)] = make_float2(h2[0][j], h2[1][j]);
            }
        }
        __threadfence();               // h^t visible before arrival signal
        {   // prefetch Wout chunk 0
            float4 wv = *(const float4*)&Wout[tid * 4];
            *(float4*)&sW0[tid * 4] = wv;
        }
        __syncthreads();               // fences done; h_t staging visible
        if (tid == 0) atomicAdd(&g_bar[b * TT + t], 1u);

        // ---------------- Phase B3: output GEMM, Xi in registers -------------
        u64 oa[2] = {};
        #pragma unroll 1
        for (int ch = 0; ch < 4; ch++) {
            const float* cw = (ch & 1) ? sW1 : sW0;
            if (ch < 3) {
                float* nw = (ch & 1) ? sW0 : sW1;
                float4 wv = *(const float4*)&Wout[(ch + 1) * 2048 + tid * 4];
                *(float4*)&nw[tid * 4] = wv;
            }
            #pragma unroll
            for (int k = 0; k < 32; k++) {
                int kg = ch * 32 + k;
                const int sw = ((k >> 2) & 7) << 2;
                const int q0 = r0O ^ sw;
                ulonglong2 aA = *(ulonglong2*)&sXT[kg * 32 + q0];
                u64 wd = pk2(cw[k * 64 + colO]);
                ffma2(oa[0], aA.x, wd); ffma2(oa[1], aA.y, wd);
            }
            __syncthreads();
        }
        #pragma unroll
        for (int p = 0; p < 2; p++) {
            float2 hv = up2(oa[p]);
            Xi[p * 2 + 0] += hv.x + boutv;
            Xi[p * 2 + 1] += hv.y + boutv;
            size_t gn0 = (size_t)(nodeBase + r0O + 2 * p);
            out[(gn0 * TT + t) * NINF + colO]       = Xi[p * 2 + 0];
            out[((gn0 + 1) * TT + t) * NINF + colO] = Xi[p * 2 + 1];
        }
    }
}

// ---------------- launch -----------------------------------------------------

extern "C" void kernel_launch(void* const* d_in, const int* in_sizes, int n_in,
                              void* d_out, int out_size) {
    (void)in_sizes; (void)n_in; (void)out_size;
    const float* X    = (const float*)d_in[0];
    const float* A    = (const float*)d_in[1];
    const float* Wse  = (const float*)d_in[2];
    const float* bse  = (const float*)d_in[3];
    const float* Wpe  = (const float*)d_in[4];
    const float* bpe  = (const float*)d_in[5];
    const float* Wii  = (const float*)d_in[6];
    const float* bii  = (const float*)d_in[7];
    const float* Whi  = (const float*)d_in[8];
    const float* bhi  = (const float*)d_in[9];
    const float* Wif  = (const float*)d_in[10];
    const float* bif  = (const float*)d_in[11];
    const float* Whf  = (const float*)d_in[12];
    const float* bhf  = (const float*)d_in[13];
    const float* Wig  = (const float*)d_in[14];
    const float* bgg  = (const float*)d_in[15];
    const float* Whg  = (const float*)d_in[16];
    const float* bhg  = (const float*)d_in[17];
    const float* Wio  = (const float*)d_in[18];
    const float* bio  = (const float*)d_in[19];
    const float* Who  = (const float*)d_in[20];
    const float* bho  = (const float*)d_in[21];
    const float* Wout = (const float*)d_in[22];
    const float* bout = (const float*)d_in[23];
    float* out = (float*)d_out;

    k_degnorm<<<8, 1024>>>(A);
    k_w2cb<<<128, 256>>>(Wpe, bpe, Wii, Wif, Wig, Wio, Whi, Whf, Whg, Who,
                         bii, bif, bgg, bio, bhi, bhf, bhg, bho);
    k_node<<<4096, 128>>>(X, Wse, bse, Wii, Wif, Wig, Wio, out);
    k_persist<<<128, 512>>>(X, Wout, bout, out);
}

// round 14
// speedup vs baseline: 1.2892x; 1.0141x over previous
#include <cuda_runtime.h>

#define BB   8
#define NN   512
#define TT   64
#define NINF 64
#define NH   128
#define NODES (BB*NN)   // 4096
#define HNELEM (NODES*NH)

// ---------------- scratch (device globals; no allocation allowed) ----------
__device__ float g_An[BB*NN*NN];      // normalized adjacency, 8.4 MB
__device__ float g_W2[256*512];       // gate-interleaved: [k][j][g], g fastest
__device__ float g_cb[512];           // per-gate constant bias (g*128+j order)
__device__ float g_C[NODES*512];      // per-node constants: [node][j][g]
__device__ float g_hpp[2*HNELEM];     // double-buffered hidden state
__device__ unsigned g_bar[BB*TT];     // per-batch per-step arrival counters

typedef unsigned long long u64;

__device__ __forceinline__ u64 pk2(float x) {
    u64 r; asm("mov.b64 %0, {%1,%1};" : "=l"(r) : "f"(x)); return r;
}
__device__ __forceinline__ void ffma2(u64 &d, u64 a, u64 b) {
    asm("fma.rn.f32x2 %0, %1, %2, %0;" : "+l"(d) : "l"(a), "l"(b));
}
__device__ __forceinline__ float2 up2(u64 v) {
    float2 r; asm("mov.b64 {%0, %1}, %2;" : "=f"(r.x), "=f"(r.y) : "l"(v)); return r;
}

__device__ __forceinline__ float sigm(float x)  { return 1.0f / (1.0f + __expf(-x)); }
__device__ __forceinline__ float tanhf_(float x){ return 2.0f / (1.0f + __expf(-2.0f*x)) - 1.0f; }

// ---------------- setup kernel 1: degrees + normalize + zero barriers -------
__global__ void __launch_bounds__(1024) k_degnorm(const float* __restrict__ A) {
    __shared__ float sdinv[NN];
    int b = blockIdx.x, tid = threadIdx.x;
    int wid = tid >> 5, lane = tid & 31;
    const float* Ab = A + (size_t)b * NN * NN;
    #pragma unroll 1
    for (int rr = 0; rr < 16; rr++) {
        int row = wid * 16 + rr;
        float s = 0.f;
        #pragma unroll
        for (int m = lane; m < NN; m += 32) s += Ab[row * NN + m];
        #pragma unroll
        for (int o = 16; o; o >>= 1) s += __shfl_down_sync(0xffffffffu, s, o);
        if (lane == 0) sdinv[row] = (s > 0.f) ? rsqrtf(s) : 0.f;
    }
    if (tid < TT) g_bar[b * TT + tid] = 0u;
    __syncthreads();
    const float4* A4 = (const float4*)Ab;
    float4* An4 = (float4*)(g_An + (size_t)b * NN * NN);
    #pragma unroll 1
    for (int i = 0; i < 64; i++) {
        int idx = tid + i * 1024;
        int row = idx >> 7, m4 = idx & 127;
        float di = sdinv[row];
        float4 a = A4[idx];
        const float* dj = sdinv + m4 * 4;
        float4 r;
        r.x = a.x * di * dj[0];
        r.y = a.y * di * dj[1];
        r.z = a.z * di * dj[2];
        r.w = a.w * di * dj[3];
        An4[idx] = r;
    }
}

// ---------------- setup kernel 2: W2 (gate-interleaved) + cb ----------------
// grid 128 (one block per k of the top half), block 256
__global__ void k_w2cb(const float* __restrict__ Wpe, const float* __restrict__ bpe,
                       const float* Wii, const float* Wif, const float* Wig, const float* Wio,
                       const float* Whi, const float* Whf, const float* Whg, const float* Who,
                       const float* bii, const float* bif, const float* bgg, const float* bio,
                       const float* bhi, const float* bhf, const float* bhg, const float* bho) {
    __shared__ float sp[128];
    int k = blockIdx.x;
    if (threadIdx.x < 128) sp[threadIdx.x] = Wpe[k * 128 + threadIdx.x];
    __syncthreads();
    for (int c = threadIdx.x; c < 512; c += blockDim.x) {
        int j = c >> 2, g = c & 3;
        const float* Wg = (g == 0) ? Wii : (g == 1) ? Wif : (g == 2) ? Wig : Wio;
        const float* Wh = (g == 0) ? Whi : (g == 1) ? Whf : (g == 2) ? Whg : Who;
        float s = 0.f;
        #pragma unroll 8
        for (int r = 0; r < 128; r++) s += sp[r] * Wg[(128 + r) * 128 + j];
        g_W2[k * 512 + j * 4 + g]         = s;          // top half: Wpe-folded
        g_W2[(128 + k) * 512 + j * 4 + g] = Wh[k * 128 + j];  // bottom: Wh
    }
    if (blockIdx.x == 0) {
        for (int c = threadIdx.x; c < 512; c += blockDim.x) {
            int g = c >> 7, j = c & 127;
            const float* Wg = (g == 0) ? Wii : (g == 1) ? Wif : (g == 2) ? Wig : Wio;
            const float* bi = (g == 0) ? bii : (g == 1) ? bif : (g == 2) ? bgg : bio;
            const float* bh = (g == 0) ? bhi : (g == 1) ? bhf : (g == 2) ? bhg : bho;
            float s = bi[j] + bh[j];
            #pragma unroll 8
            for (int r = 0; r < 128; r++) s += bpe[r] * Wg[(128 + r) * 128 + j];
            g_cb[c] = s;
        }
    }
}

// ---------------- setup kernel 3: per-node constants + out[t=0] -------------
// grid 4096, block 128; g_C stored [node][j][g]
__global__ void k_node(const float* __restrict__ X,
                       const float* __restrict__ Wse, const float* __restrict__ bse,
                       const float* Wii, const float* Wif, const float* Wig, const float* Wio,
                       float* __restrict__ out) {
    __shared__ float sx0[64];
    __shared__ float ses[128];
    int node = blockIdx.x;
    int j = threadIdx.x;
    size_t xbase = (size_t)node * TT * NINF;
    if (j < 64) { float v = X[xbase + j]; sx0[j] = v; out[xbase + j] = v; }
    __syncthreads();
    float e = bse[j];
    #pragma unroll 8
    for (int k = 0; k < 64; k++) e += sx0[k] * Wse[k * 128 + j];
    ses[j] = e;
    __syncthreads();
    #pragma unroll
    for (int g = 0; g < 4; g++) {
        const float* Wg = (g == 0) ? Wii : (g == 1) ? Wif : (g == 2) ? Wig : Wio;
        float s = g_cb[g * 128 + j];
        #pragma unroll 8
        for (int k = 0; k < 128; k++) s += ses[k] * Wg[k * 128 + j];
        g_C[((size_t)node * 128 + j) * 4 + g] = s;
    }
}

// ---------------- persistent per-step kernel ---------------------------------
// grid 128 (= 8 batches x 16 row-tiles of 32), block 512 (16 warps), 63 steps.
// Dynamic smem 64 KB: sXT (32 KB) + 2 weight tile buffers (16 KB each).
__global__ void __launch_bounds__(512, 1) k_persist(const float* __restrict__ X,
                                                    const float* __restrict__ Wout,
                                                    const float* __restrict__ bout,
                                                    float* __restrict__ out) {
    extern __shared__ __align__(16) float smem[];
    float* sXT = smem;                 // [k 0..255][r 0..31], XOR swizzle
    float* sW0 = smem + 8192;          // weight buffer 0 (4096 floats)
    float* sW1 = smem + 12288;         // weight buffer 1
    // Phase A double buffers at p*5120: An^T (1024) | h tile (4096); p=1 spills
    // into sW0's first 2048 floats — consumed before sW0 is first written.

    const int tid  = threadIdx.x;
    const int w    = tid >> 5;
    const int lane = tid & 31;
    const int b    = blockIdx.x >> 4;
    const int row0 = (blockIdx.x & 15) * 32;
    const int nodeBase = b * NN + row0;
    const float* An = g_An + (size_t)b * NN * NN;

    // Phase A compute mapping (warps 0-7): 4 rows (2 pairs) x 4 feats per lane
    const int r0A = (lane & 7) * 4;
    const int fgA = lane >> 3;
    const int f0A = w * 16 + fgA * 4;          // valid for w<8
    // Phase A producer mapping (warps 8-15)
    const int ptid = tid - 256;
    const int kk4  = ptid & 7;
    const int rL   = ptid >> 3;
    // Phase B1/B2 mapping: 8 rows (4 pairs) x 1 j x 4 gates per lane
    const int r0B = (lane & 3) * 8;
    const int jB  = w * 8 + (lane >> 2);       // 0..127
    // Phase B3 mapping: 4 rows x 1 col per lane
    const int r0O  = (lane & 7) * 4;
    const int colO = w * 4 + (lane >> 3);      // 0..63

    // persistent register state: c (8 rows @ jB) and running output Xi
    float2 creg[4];
    #pragma unroll
    for (int p = 0; p < 4; p++) creg[p] = make_float2(0.f, 0.f);
    float Xi[4];
    #pragma unroll
    for (int q = 0; q < 4; q++)
        Xi[q] = X[(size_t)(nodeBase + r0O + q) * (TT * NINF) + colO];
    const float boutv = bout[colO];

    volatile unsigned* barv = (volatile unsigned*)g_bar;

    #pragma unroll 1
    for (int t = 1; t < TT; t++) {
        const float* hr = g_hpp + ((t - 1) & 1) * HNELEM;
        float*       hw = g_hpp + (t & 1)       * HNELEM;
        u64 acc[4][4] = {};            // [row pair][gate], rows r0B+2p, r0B+2p+1 @ jB

        if (t > 1) {
            // producers preload An kb=0 (independent of h) while tid0 spins
            if (w >= 8) {
                float* sAT = smem;
                float4 v = *(const float4*)&An[(size_t)(row0 + rL) * NN + kk4 * 4];
                int rsw = rL ^ (kk4 << 2);
                sAT[(kk4 * 4 + 0) * 32 + rsw] = v.x;
                sAT[(kk4 * 4 + 1) * 32 + rsw] = v.y;
                sAT[(kk4 * 4 + 2) * 32 + rsw] = v.z;
                sAT[(kk4 * 4 + 3) * 32 + rsw] = v.w;
            }
            if (tid == 0) { while (barv[b * TT + (t - 1)] < 16u) { } }
            __syncthreads();           // h^{t-1} visible to whole block

            if (w >= 8) {              // h tile kb=0
                float* sB = smem + 1024;
                #pragma unroll
                for (int p2 = 0; p2 < 4; p2++) {
                    int id = ptid + p2 * 256;
                    int kL = id >> 5, f4 = id & 31;
                    float4 hv = __ldcg((const float4*)&hr[(size_t)(b * NN + kL) * NH + f4 * 4]);
                    *(float4*)&sB[kL * 128 + f4 * 4] = hv;
                }
            }
            __syncthreads();

            // ---------------- Phase A: H = An_tile @ h (producer/consumer) --
            u64 accA[2][4] = {};
            #pragma unroll 1
            for (int kb = 0; kb < 16; kb++) {
                if (w >= 8) {
                    if (kb < 15) {
                        float* sAT = smem + ((kb + 1) & 1) * 5120;
                        float* sB  = sAT + 1024;
                        float4 v = *(const float4*)
                            &An[(size_t)(row0 + rL) * NN + (kb + 1) * 32 + kk4 * 4];
                        int rsw = rL ^ (kk4 << 2);
                        sAT[(kk4 * 4 + 0) * 32 + rsw] = v.x;
                        sAT[(kk4 * 4 + 1) * 32 + rsw] = v.y;
                        sAT[(kk4 * 4 + 2) * 32 + rsw] = v.z;
                        sAT[(kk4 * 4 + 3) * 32 + rsw] = v.w;
                        #pragma unroll
                        for (int p2 = 0; p2 < 4; p2++) {
                            int id = ptid + p2 * 256;
                            int kL = id >> 5, f4 = id & 31;
                            float4 hv = __ldcg((const float4*)
                                &hr[(size_t)(b * NN + (kb + 1) * 32 + kL) * NH + f4 * 4]);
                            *(float4*)&sB[kL * 128 + f4 * 4] = hv;
                        }
                    }
                } else {
                    const float* sAT = smem + (kb & 1) * 5120;
                    const float* sB  = sAT + 1024;
                    #pragma unroll
                    for (int k = 0; k < 32; k++) {
                        const int sw = ((k >> 2) & 7) << 2;
                        ulonglong2 ap = *(ulonglong2*)&sAT[k * 32 + (r0A ^ sw)];
                        float4 bf = *(float4*)&sB[k * 128 + f0A];
                        u64 b0 = pk2(bf.x), b1 = pk2(bf.y), b2 = pk2(bf.z), b3 = pk2(bf.w);
                        ffma2(accA[0][0], ap.x, b0); ffma2(accA[0][1], ap.x, b1);
                        ffma2(accA[0][2], ap.x, b2); ffma2(accA[0][3], ap.x, b3);
                        ffma2(accA[1][0], ap.y, b0); ffma2(accA[1][1], ap.y, b1);
                        ffma2(accA[1][2], ap.y, b2); ffma2(accA[1][3], ap.y, b3);
                    }
                }
                __syncthreads();
            }

            // H -> sXT rows 0..127 (transposed, swizzled) by warps 0-7
            if (w < 8) {
                const int swH = ((w * 4 + fgA) & 7) << 2;
                #pragma unroll
                for (int ff = 0; ff < 4; ff++)
                    #pragma unroll
                    for (int p2 = 0; p2 < 2; p2++)
                        *(u64*)&sXT[(f0A + ff) * 32 + ((r0A + 2 * p2) ^ swH)] = accA[p2][ff];
            }
            // own h tile -> rows 128..255 (all threads, 2 float4 each)
            #pragma unroll
            for (int p2 = 0; p2 < 2; p2++) {
                int id = tid + p2 * 512;
                int r = id & 31, f4 = id >> 5;
                float4 v = __ldcg((const float4*)&hr[(size_t)(nodeBase + r) * NH + f4 * 4]);
                int rsw = r ^ ((f4 & 7) << 2);
                sXT[(128 + f4 * 4 + 0) * 32 + rsw] = v.x;
                sXT[(128 + f4 * 4 + 1) * 32 + rsw] = v.y;
                sXT[(128 + f4 * 4 + 2) * 32 + rsw] = v.z;
                sXT[(128 + f4 * 4 + 3) * 32 + rsw] = v.w;
            }
            {   // prefetch W2 k-tile 0 (8 k rows = 4096 floats; 8 per thread)
                float4 w0 = __ldcg((const float4*)&g_W2[tid * 8]);
                float4 w1 = __ldcg((const float4*)&g_W2[tid * 8 + 4]);
                *(float4*)&sW0[tid * 8] = w0; *(float4*)&sW0[tid * 8 + 4] = w1;
            }
            __syncthreads();

            // ---------------- Phase B1: gate GEMM, 8-k tiles -----------------
            #pragma unroll 1
            for (int kt = 0; kt < 32; kt++) {
                const float* cw = (kt & 1) ? sW1 : sW0;
                if (kt < 31) {
                    float* nw = (kt & 1) ? sW0 : sW1;
                    float4 w0 = __ldcg((const float4*)&g_W2[(kt + 1) * 4096 + tid * 8]);
                    float4 w1 = __ldcg((const float4*)&g_W2[(kt + 1) * 4096 + tid * 8 + 4]);
                    *(float4*)&nw[tid * 8] = w0; *(float4*)&nw[tid * 8 + 4] = w1;
                }
                #pragma unroll
                for (int kk = 0; kk < 8; kk++) {
                    const int k = kt * 8 + kk;
                    const int sw = ((k >> 2) & 7) << 2;
                    const int q0 = r0B ^ sw;
                    const float* xk = &sXT[k * 32];
                    ulonglong2 aA = *(ulonglong2*)&xk[q0];       // rows r0B..+3
                    ulonglong2 aB = *(ulonglong2*)&xk[q0 ^ 4];   // rows r0B+4..+7
                    float4 wv = *(float4*)&cw[kk * 512 + jB * 4];  // 4 gates @ jB
                    u64 w0 = pk2(wv.x), w1 = pk2(wv.y), w2 = pk2(wv.z), w3 = pk2(wv.w);
                    ffma2(acc[0][0], aA.x, w0); ffma2(acc[0][1], aA.x, w1);
                    ffma2(acc[0][2], aA.x, w2); ffma2(acc[0][3], aA.x, w3);
                    ffma2(acc[1][0], aA.y, w0); ffma2(acc[1][1], aA.y, w1);
                    ffma2(acc[1][2], aA.y, w2); ffma2(acc[1][3], aA.y, w3);
                    ffma2(acc[2][0], aB.x, w0); ffma2(acc[2][1], aB.x, w1);
                    ffma2(acc[2][2], aB.x, w2); ffma2(acc[2][3], aB.x, w3);
                    ffma2(acc[3][0], aB.y, w0); ffma2(acc[3][1], aB.y, w1);
                    ffma2(acc[3][2], aB.y, w2); ffma2(acc[3][3], aB.y, w3);
                }
                __syncthreads();
            }
        } else {
            __syncthreads();
        }

        // ---------------- Phase B2: LSTM elementwise (c in registers) --------
        // lane: rows r0B..r0B+7 (4 pairs), feature jB, all 4 gates in acc[p][g]
        #pragma unroll
        for (int p = 0; p < 4; p++) {
            float2 ui = up2(acc[p][0]);
            float2 uf = up2(acc[p][1]);
            float2 ug = up2(acc[p][2]);
            float2 uo = up2(acc[p][3]);
            float2 cold = creg[p];
            float h2[2], cn[2];
            #pragma unroll
            for (int rr = 0; rr < 2; rr++) {
                size_t gn = (size_t)(nodeBase + r0B + 2 * p + rr);
                float4 C4 = *(const float4*)&g_C[(gn * 128 + jB) * 4];
                float ig = sigm  ((rr ? ui.y : ui.x) + C4.x);
                float fg = sigm  ((rr ? uf.y : uf.x) + C4.y);
                float gg = tanhf_((rr ? ug.y : ug.x) + C4.z);
                float og = sigm  ((rr ? uo.y : uo.x) + C4.w);
                float cc = fg * (rr ? cold.y : cold.x) + ig * gg;
                cn[rr] = cc;
                h2[rr] = og * tanhf_(cc);
                __stcg(&hw[gn * 128 + jB], h2[rr]);
            }
            creg[p] = make_float2(cn[0], cn[1]);
            // stage h_t transposed into sXT (feature-major), swizzled
            const int swj = ((jB >> 2) & 7) << 2;
            *(float2*)&sXT[jB * 32 + ((r0B + 2 * p) ^ swj)] = make_float2(h2[0], h2[1]);
        }
        __threadfence();               // h^t visible before arrival signal
        {   // prefetch Wout chunk 0 (2048 floats; 4 per thread)
            float4 wv = *(const float4*)&Wout[tid * 4];
            *(float4*)&sW0[tid * 4] = wv;
        }
        __syncthreads();               // fences done; h_t staging visible
        if (tid == 0) atomicAdd(&g_bar[b * TT + t], 1u);

        // ---------------- Phase B3: output GEMM, Xi in registers -------------
        u64 oa[2] = {};
        #pragma unroll 1
        for (int ch = 0; ch < 4; ch++) {
            const float* cw = (ch & 1) ? sW1 : sW0;
            if (ch < 3) {
                float* nw = (ch & 1) ? sW0 : sW1;
                float4 wv = *(const float4*)&Wout[(ch + 1) * 2048 + tid * 4];
                *(float4*)&nw[tid * 4] = wv;
            }
            #pragma unroll
            for (int k = 0; k < 32; k++) {
                int kg = ch * 32 + k;
                const int sw = ((k >> 2) & 7) << 2;
                const int q0 = r0O ^ sw;
                ulonglong2 aA = *(ulonglong2*)&sXT[kg * 32 + q0];
                u64 wd = pk2(cw[k * 64 + colO]);
                ffma2(oa[0], aA.x, wd); ffma2(oa[1], aA.y, wd);
            }
            __syncthreads();
        }
        #pragma unroll
        for (int p = 0; p < 2; p++) {
            float2 hv = up2(oa[p]);
            Xi[p * 2 + 0] += hv.x + boutv;
            Xi[p * 2 + 1] += hv.y + boutv;
            size_t gn0 = (size_t)(nodeBase + r0O + 2 * p);
            out[(gn0 * TT + t) * NINF + colO]       = Xi[p * 2 + 0];
            out[((gn0 + 1) * TT + t) * NINF + colO] = Xi[p * 2 + 1];
        }
    }
}

// ---------------- launch -----------------------------------------------------

extern "C" void kernel_launch(void* const* d_in, const int* in_sizes, int n_in,
                              void* d_out, int out_size) {
    (void)in_sizes; (void)n_in; (void)out_size;
    const float* X    = (const float*)d_in[0];
    const float* A    = (const float*)d_in[1];
    const float* Wse  = (const float*)d_in[2];
    const float* bse  = (const float*)d_in[3];
    const float* Wpe  = (const float*)d_in[4];
    const float* bpe  = (const float*)d_in[5];
    const float* Wii  = (const float*)d_in[6];
    const float* bii  = (const float*)d_in[7];
    const float* Whi  = (const float*)d_in[8];
    const float* bhi  = (const float*)d_in[9];
    const float* Wif  = (const float*)d_in[10];
    const float* bif  = (const float*)d_in[11];
    const float* Whf  = (const float*)d_in[12];
    const float* bhf  = (const float*)d_in[13];
    const float* Wig  = (const float*)d_in[14];
    const float* bgg  = (const float*)d_in[15];
    const float* Whg  = (const float*)d_in[16];
    const float* bhg  = (const float*)d_in[17];
    const float* Wio  = (const float*)d_in[18];
    const float* bio  = (const float*)d_in[19];
    const float* Who  = (const float*)d_in[20];
    const float* bho  = (const float*)d_in[21];
    const float* Wout = (const float*)d_in[22];
    const float* bout = (const float*)d_in[23];
    float* out = (float*)d_out;

    static int smem_set = 0;
    cudaFuncSetAttribute(k_persist, cudaFuncAttributeMaxDynamicSharedMemorySize, 65536);
    (void)smem_set;

    k_degnorm<<<8, 1024>>>(A);
    k_w2cb<<<128, 256>>>(Wpe, bpe, Wii, Wif, Wig, Wio, Whi, Whf, Whg, Who,
                         bii, bif, bgg, bio, bhi, bhf, bhg, bho);
    k_node<<<4096, 128>>>(X, Wse, bse, Wii, Wif, Wig, Wio, out);
    k_persist<<<128, 512, 65536>>>(X, Wout, bout, out);
}